// round 2
// baseline (speedup 1.0000x reference)
#include <cuda_runtime.h>
#include <math.h>

typedef unsigned long long ull;

// ---------------- model dims ----------------
#define NDEPTH 6
#define DMODEL 1024
#define NHEADS 16
#define DHEAD  64
#define SEQ    1024
#define BATCH  4
#define MROWS  (BATCH*SEQ)        // 4096
#define FFI    4096               // FF_INNER
#define BH     (BATCH*NHEADS)     // 64

// ---------------- scratch (static device memory; no allocs allowed) ----------------
__device__ float g_xbuf [MROWS*DMODEL];
__device__ float g_lnbuf[MROWS*DMODEL];
__device__ float g_qkv  [MROWS*3*DMODEL];
__device__ float g_S    [(size_t)BH*SEQ*SEQ];     // 256 MB attention scores/probs
__device__ float g_attno[MROWS*DMODEL];
__device__ float g_proj [MROWS*DMODEL];
__device__ float g_ff1  [(size_t)MROWS*2*FFI];    // 128 MB
__device__ float g_geglu[(size_t)MROWS*FFI];
__device__ float g_ffln [(size_t)MROWS*FFI];

// ---------------- LayerNorm (biased var, no bias), optional fused residual ----------------
// out[r,c] = (x[r,c]-mean)*rsqrt(var+eps)*g[c] (+ res[r,c])
__global__ void ln_kernel(const float* __restrict__ in, const float* __restrict__ g,
                          const float* __restrict__ res, float* __restrict__ out, int D)
{
    int row = blockIdx.x;
    const float* x = in + (size_t)row * D;
    float s = 0.f, sq = 0.f;
    for (int c = threadIdx.x; c < D; c += blockDim.x) { float v = x[c]; s += v; sq += v*v; }
    __shared__ float sh[64];
    for (int o = 16; o; o >>= 1) { s += __shfl_xor_sync(0xffffffffu, s, o); sq += __shfl_xor_sync(0xffffffffu, sq, o); }
    int wid = threadIdx.x >> 5, lid = threadIdx.x & 31;
    if (lid == 0) { sh[wid] = s; sh[wid + 32] = sq; }
    __syncthreads();
    if (wid == 0) {
        int nw = blockDim.x >> 5;
        float a = (lid < nw) ? sh[lid] : 0.f;
        float b = (lid < nw) ? sh[lid + 32] : 0.f;
        for (int o = 16; o; o >>= 1) { a += __shfl_xor_sync(0xffffffffu, a, o); b += __shfl_xor_sync(0xffffffffu, b, o); }
        if (lid == 0) { sh[0] = a; sh[1] = b; }
    }
    __syncthreads();
    float mean = sh[0] / D;
    float var  = sh[1] / D - mean * mean;
    float rstd = rsqrtf(var + 1e-5f);
    float* o = out + (size_t)row * D;
    const float* rr = res ? res + (size_t)row * D : nullptr;
    for (int c = threadIdx.x; c < D; c += blockDim.x) {
        float v = (x[c] - mean) * rstd * g[c];
        if (rr) v += rr[c];
        o[c] = v;
    }
}

// ---------------- SGEMM: C[M,N] = A[M,K] * B[K,N], row-major, fp32 via fma.rn.f32x2 ----------------
// 128x128 tile, BK=16, 256 threads, each thread owns a 2x2 grid of 4x4 sub-blocks
// (rows {ty*4..+3, 64+ty*4..+3}, cols {tx*4..+3, 64+tx*4..+3}); accumulators are
// packed f32x2 pairs so the FMA pipe runs at dual rate (FFMA2 pattern).
__global__ __launch_bounds__(256)
void sgemm_f32x2(const float* __restrict__ A, const float* __restrict__ B,
                 float* __restrict__ C, int M, int N, int K)
{
    const int BM = 128, BN = 128, BK = 16;
    __shared__ float As[BK][BM];
    __shared__ float Bs[BK][BN];
    int tid = threadIdx.x;
    int bm = blockIdx.y * BM, bn = blockIdx.x * BN;
    int tx = tid & 15, ty = tid >> 4;

    ull acc[8][4];
#pragma unroll
    for (int i = 0; i < 8; i++)
#pragma unroll
        for (int j = 0; j < 4; j++) acc[i][j] = 0ull;

    for (int k0 = 0; k0 < K; k0 += BK) {
        // load A tile (BM x BK), stored transposed As[k][m]
#pragma unroll
        for (int idx = tid; idx < BM * BK / 4; idx += 256) {
            int r = idx / (BK / 4), c4 = idx % (BK / 4);
            float4 v = *(const float4*)(A + (size_t)(bm + r) * K + k0 + c4 * 4);
            As[c4 * 4 + 0][r] = v.x; As[c4 * 4 + 1][r] = v.y;
            As[c4 * 4 + 2][r] = v.z; As[c4 * 4 + 3][r] = v.w;
        }
        // load B tile (BK x BN)
#pragma unroll
        for (int idx = tid; idx < BK * BN / 4; idx += 256) {
            int r = idx / (BN / 4), c4 = idx % (BN / 4);
            *(float4*)&Bs[r][c4 * 4] = *(const float4*)(B + (size_t)(k0 + r) * N + bn + c4 * 4);
        }
        __syncthreads();
#pragma unroll
        for (int k = 0; k < BK; k++) {
            ull a2[8], b2[4];
#pragma unroll
            for (int ih = 0; ih < 2; ih++) {
                float4 av = *(const float4*)&As[k][ih * 64 + ty * 4];
                asm("mov.b64 %0, {%1, %1};" : "=l"(a2[ih * 4 + 0]) : "f"(av.x));
                asm("mov.b64 %0, {%1, %1};" : "=l"(a2[ih * 4 + 1]) : "f"(av.y));
                asm("mov.b64 %0, {%1, %1};" : "=l"(a2[ih * 4 + 2]) : "f"(av.z));
                asm("mov.b64 %0, {%1, %1};" : "=l"(a2[ih * 4 + 3]) : "f"(av.w));
            }
#pragma unroll
            for (int jh = 0; jh < 2; jh++) {
                float4 bv = *(const float4*)&Bs[k][jh * 64 + tx * 4];
                asm("mov.b64 %0, {%1, %2};" : "=l"(b2[jh * 2 + 0]) : "f"(bv.x), "f"(bv.y));
                asm("mov.b64 %0, {%1, %2};" : "=l"(b2[jh * 2 + 1]) : "f"(bv.z), "f"(bv.w));
            }
#pragma unroll
            for (int i = 0; i < 8; i++)
#pragma unroll
                for (int j = 0; j < 4; j++)
                    asm("fma.rn.f32x2 %0, %1, %2, %0;" : "+l"(acc[i][j]) : "l"(a2[i]), "l"(b2[j]));
        }
        __syncthreads();
    }
#pragma unroll
    for (int i = 0; i < 8; i++) {
        int row = bm + ((i < 4) ? (ty * 4 + i) : (64 + ty * 4 + (i - 4)));
#pragma unroll
        for (int j = 0; j < 4; j++) {
            int col = bn + ((j < 2) ? (tx * 4 + j * 2) : (64 + tx * 4 + (j - 2) * 2));
            *(float2*)(C + (size_t)row * N + col) = *(float2*)&acc[i][j];
        }
    }
}

// ---------------- attention: S = scale * Q K^T (per b,h), 64x64 tiles, skip masked tiles ----------------
__global__ void qk_kernel(const float* __restrict__ qkv, float* __restrict__ S)
{
    int bh = blockIdx.z; int b = bh >> 4, h = bh & 15;
    int jt = blockIdx.x, it = blockIdx.y;
    if (jt > it) return;  // fully masked tile; softmax writes zeros there
    __shared__ float Qs[64][68];
    __shared__ float Ks[64][68];
    int tid = threadIdx.x;
    const float* qbase = qkv + (size_t)(b * SEQ + it * 64) * (3 * DMODEL) + h * DHEAD;
    const float* kbase = qkv + (size_t)(b * SEQ + jt * 64) * (3 * DMODEL) + DMODEL + h * DHEAD;
#pragma unroll
    for (int idx = tid; idx < 64 * 16; idx += 256) {
        int r = idx / 16, c4 = idx % 16;
        *(float4*)&Qs[r][c4 * 4] = *(const float4*)(qbase + (size_t)r * (3 * DMODEL) + c4 * 4);
        *(float4*)&Ks[r][c4 * 4] = *(const float4*)(kbase + (size_t)r * (3 * DMODEL) + c4 * 4);
    }
    __syncthreads();
    int tx = tid & 15, ty = tid >> 4;
    float acc[4][4] = {};
#pragma unroll
    for (int d = 0; d < 64; d++) {
        float a[4], bb[4];
#pragma unroll
        for (int i = 0; i < 4; i++) a[i] = Qs[ty * 4 + i][d];
#pragma unroll
        for (int j = 0; j < 4; j++) bb[j] = Ks[tx * 4 + j][d];
#pragma unroll
        for (int i = 0; i < 4; i++)
#pragma unroll
            for (int j = 0; j < 4; j++) acc[i][j] += a[i] * bb[j];
    }
    const float scale = 0.125f; // DHEAD^-0.5
    float* srow = S + ((size_t)bh << 20) + (size_t)(it * 64) * SEQ + jt * 64;
#pragma unroll
    for (int i = 0; i < 4; i++)
#pragma unroll
        for (int j = 0; j < 4; j++)
            srow[(size_t)(ty * 4 + i) * SEQ + tx * 4 + j] = acc[i][j] * scale;
}

// ---------------- row softmax over valid prefix j<=i, zeros elsewhere ----------------
__global__ void softmax_kernel(float* __restrict__ S)
{
    int row = blockIdx.x;            // bh*1024 + i
    int i = row & (SEQ - 1);
    float* p = S + (size_t)row * SEQ;
    int L = i + 1;
    int tid = threadIdx.x;
    __shared__ float sh[32];
    float m = -3.4028235e38f;
    for (int j = tid; j < L; j += 256) m = fmaxf(m, p[j]);
    for (int o = 16; o; o >>= 1) m = fmaxf(m, __shfl_xor_sync(0xffffffffu, m, o));
    if ((tid & 31) == 0) sh[tid >> 5] = m;
    __syncthreads();
    if (tid < 32) {
        float v = (tid < 8) ? sh[tid] : -3.4028235e38f;
        for (int o = 4; o; o >>= 1) v = fmaxf(v, __shfl_xor_sync(0xffffffffu, v, o));
        if (tid == 0) sh[0] = v;
    }
    __syncthreads();
    m = sh[0];
    __syncthreads();
    float s = 0.f;
    for (int j = tid; j < L; j += 256) { float e = expf(p[j] - m); p[j] = e; s += e; }
    for (int o = 16; o; o >>= 1) s += __shfl_xor_sync(0xffffffffu, s, o);
    if ((tid & 31) == 0) sh[tid >> 5] = s;
    __syncthreads();
    if (tid < 32) {
        float v = (tid < 8) ? sh[tid] : 0.f;
        for (int o = 4; o; o >>= 1) v += __shfl_xor_sync(0xffffffffu, v, o);
        if (tid == 0) sh[0] = v;
    }
    __syncthreads();
    float inv = 1.0f / sh[0];
    for (int j = tid; j < L; j += 256) p[j] *= inv;
    for (int j = L + tid; j < SEQ; j += 256) p[j] = 0.f;
}

// ---------------- O = P @ V (per b,h), causal-truncated K-loop, writes merged-head layout ----------------
__global__ void pv_kernel(const float* __restrict__ S, const float* __restrict__ qkv,
                          float* __restrict__ out)
{
    int it = blockIdx.x;   // 16 query tiles of 64
    int bh = blockIdx.y;   // 64
    int b = bh >> 4, h = bh & 15;
    __shared__ float Ps[64][36];
    __shared__ float Vs[32][68];
    int tid = threadIdx.x;
    int tx = tid & 15, ty = tid >> 4;
    const float* sbase = S + ((size_t)bh << 20) + (size_t)(it * 64) * SEQ;
    const float* vbase = qkv + 2 * DMODEL + h * DHEAD;
    float acc[4][4] = {};
    int kend = (it + 1) * 64;
    for (int j0 = 0; j0 < kend; j0 += 32) {
#pragma unroll
        for (int idx = tid; idx < 64 * 8; idx += 256) {
            int r = idx / 8, c4 = idx % 8;
            *(float4*)&Ps[r][c4 * 4] = *(const float4*)(sbase + (size_t)r * SEQ + j0 + c4 * 4);
        }
#pragma unroll
        for (int idx = tid; idx < 32 * 16; idx += 256) {
            int r = idx / 16, c4 = idx % 16;
            *(float4*)&Vs[r][c4 * 4] =
                *(const float4*)(vbase + (size_t)(b * SEQ + j0 + r) * (3 * DMODEL) + c4 * 4);
        }
        __syncthreads();
#pragma unroll
        for (int jj = 0; jj < 32; jj++) {
            float a[4], vv[4];
#pragma unroll
            for (int i = 0; i < 4; i++) a[i] = Ps[ty * 4 + i][jj];
#pragma unroll
            for (int d = 0; d < 4; d++) vv[d] = Vs[jj][tx * 4 + d];
#pragma unroll
            for (int i = 0; i < 4; i++)
#pragma unroll
                for (int d = 0; d < 4; d++) acc[i][d] += a[i] * vv[d];
        }
        __syncthreads();
    }
#pragma unroll
    for (int i = 0; i < 4; i++) {
        size_t row = (size_t)(b * SEQ + it * 64 + ty * 4 + i) * DMODEL + h * DHEAD + tx * 4;
#pragma unroll
        for (int d = 0; d < 4; d++) out[row + d] = acc[i][d];
    }
}

// ---------------- GEGLU: o = a * gelu_exact(gate) ----------------
__global__ void geglu_kernel(const float* __restrict__ h, float* __restrict__ o)
{
    int idx = blockIdx.x * blockDim.x + threadIdx.x;   // < 4096*4096
    int m = idx >> 12, c = idx & 4095;
    float a = h[(size_t)m * (2 * FFI) + c];
    float g = h[(size_t)m * (2 * FFI) + FFI + c];
    float ge = 0.5f * g * (1.0f + erff(g * 0.70710678118654752f));
    o[idx] = a * ge;
}

__global__ void add_kernel(float* __restrict__ x, const float* __restrict__ y, int n)
{
    int i = blockIdx.x * blockDim.x + threadIdx.x;
    if (i < n) x[i] += y[i];
}

// ---------------- orchestration ----------------
extern "C" void kernel_launch(void* const* d_in, const int* in_sizes, int n_in,
                              void* d_out, int out_size)
{
    const float* x_in   = (const float*)d_in[0];
    const float* qkv_w  = (const float*)d_in[1];
    const float* out_w  = (const float*)d_in[2];
    const float* ff_w1  = (const float*)d_in[3];
    const float* ff_w2  = (const float*)d_in[4];
    const float* attn_g = (const float*)d_in[5];
    const float* outln_g= (const float*)d_in[6];
    const float* ffn_g  = (const float*)d_in[7];
    const float* ffln_g = (const float*)d_in[8];
    const float* nin_g  = (const float*)d_in[9];
    const float* nout_g = (const float*)d_in[10];
    float* out = (float*)d_out;

    float *xbuf, *lnbuf, *qkvb, *Sb, *attno, *proj, *ff1, *geg, *ffln;
    cudaGetSymbolAddress((void**)&xbuf,  g_xbuf);
    cudaGetSymbolAddress((void**)&lnbuf, g_lnbuf);
    cudaGetSymbolAddress((void**)&qkvb,  g_qkv);
    cudaGetSymbolAddress((void**)&Sb,    g_S);
    cudaGetSymbolAddress((void**)&attno, g_attno);
    cudaGetSymbolAddress((void**)&proj,  g_proj);
    cudaGetSymbolAddress((void**)&ff1,   g_ff1);
    cudaGetSymbolAddress((void**)&geg,   g_geglu);
    cudaGetSymbolAddress((void**)&ffln,  g_ffln);

    const int M = MROWS;
    // x = LN(x, norm_in_g)
    ln_kernel<<<M, 256>>>(x_in, nin_g, nullptr, xbuf, DMODEL);

    for (int l = 0; l < NDEPTH; l++) {
        // ---- attention block ----
        ln_kernel<<<M, 256>>>(xbuf, attn_g + (size_t)l * DMODEL, nullptr, lnbuf, DMODEL);
        sgemm_f32x2<<<dim3(3 * DMODEL / 128, M / 128), 256>>>(
            lnbuf, qkv_w + (size_t)l * DMODEL * 3 * DMODEL, qkvb, M, 3 * DMODEL, DMODEL);
        qk_kernel<<<dim3(16, 16, BH), 256>>>(qkvb, Sb);
        softmax_kernel<<<BH * SEQ, 256>>>(Sb);
        pv_kernel<<<dim3(16, BH), 256>>>(Sb, qkvb, attno);
        sgemm_f32x2<<<dim3(DMODEL / 128, M / 128), 256>>>(
            attno, out_w + (size_t)l * DMODEL * DMODEL, proj, M, DMODEL, DMODEL);
        // x = LN(proj, out_ln_g) + x
        ln_kernel<<<M, 256>>>(proj, outln_g + (size_t)l * DMODEL, xbuf, xbuf, DMODEL);

        // ---- GEGLU feedforward ----
        ln_kernel<<<M, 256>>>(xbuf, ffn_g + (size_t)l * DMODEL, nullptr, lnbuf, DMODEL);
        sgemm_f32x2<<<dim3(2 * FFI / 128, M / 128), 256>>>(
            lnbuf, ff_w1 + (size_t)l * DMODEL * 2 * FFI, ff1, M, 2 * FFI, DMODEL);
        geglu_kernel<<<(M * FFI) / 256, 256>>>(ff1, geg);
        ln_kernel<<<M, 256>>>(geg, ffln_g + (size_t)l * FFI, nullptr, ffln, FFI);
        sgemm_f32x2<<<dim3(DMODEL / 128, M / 128), 256>>>(
            ffln, ff_w2 + (size_t)l * FFI * DMODEL, proj, M, DMODEL, FFI);
        add_kernel<<<(M * DMODEL) / 256, 256>>>(xbuf, proj, M * DMODEL);
    }
    // out = LN(x, norm_out_g)
    ln_kernel<<<M, 256>>>(xbuf, nout_g, nullptr, out, DMODEL);
}

// round 4
// speedup vs baseline: 2.5440x; 2.5440x over previous
#include <cuda_runtime.h>
#include <cuda_bf16.h>
#include <math.h>
#include <stdint.h>

typedef unsigned long long ull;

// ---------------- model dims ----------------
#define NDEPTH 6
#define DMODEL 1024
#define NHEADS 16
#define DHEAD  64
#define SEQ    1024
#define BATCH  4
#define MROWS  (BATCH*SEQ)        // 4096
#define FFI    4096               // FF_INNER
#define BH     (BATCH*NHEADS)     // 64

// ---------------- scratch (static device memory; no allocs allowed) ----------------
__device__ float g_xbuf [MROWS*DMODEL];
__device__ float g_lnbuf[MROWS*DMODEL];
__device__ float g_qkv  [MROWS*3*DMODEL];
__device__ float g_S    [(size_t)BH*SEQ*SEQ];     // 256 MB attention scores/probs
__device__ float g_attno[MROWS*DMODEL];
__device__ float g_proj [MROWS*DMODEL];
__device__ float g_ff1  [(size_t)MROWS*2*FFI];    // 128 MB
__device__ float g_geglu[(size_t)MROWS*FFI];
__device__ float g_ffln [(size_t)MROWS*FFI];

// split-bf16 operand buffers (reused across GEMMs)
__device__ __nv_bfloat16 g_ahi[(size_t)MROWS*FFI];       // up to 4096x4096
__device__ __nv_bfloat16 g_alo[(size_t)MROWS*FFI];
__device__ __nv_bfloat16 g_bhi[(size_t)(2*FFI)*DMODEL];  // up to 8192x1024 (N-major [N,K])
__device__ __nv_bfloat16 g_blo[(size_t)(2*FFI)*DMODEL];

// ---------------- helpers ----------------
__device__ __forceinline__ uint32_t smem_u32(const void* p) {
    uint32_t a;
    asm("{ .reg .u64 t; cvta.to.shared.u64 t, %1; cvt.u32.u64 %0, t; }" : "=r"(a) : "l"(p));
    return a;
}
__device__ __forceinline__ void mma16816(float* c, const uint32_t* a, uint32_t b0, uint32_t b1) {
    asm volatile(
        "mma.sync.aligned.m16n8k16.row.col.f32.bf16.bf16.f32 "
        "{%0,%1,%2,%3}, {%4,%5,%6,%7}, {%8,%9}, {%0,%1,%2,%3};"
        : "+f"(c[0]), "+f"(c[1]), "+f"(c[2]), "+f"(c[3])
        : "r"(a[0]), "r"(a[1]), "r"(a[2]), "r"(a[3]), "r"(b0), "r"(b1));
}
#define LDSM_X4(r0, r1, r2, r3, addr) \
    asm volatile("ldmatrix.sync.aligned.m8n8.x4.shared.b16 {%0,%1,%2,%3}, [%4];" \
                 : "=r"(r0), "=r"(r1), "=r"(r2), "=r"(r3) : "r"(addr))
#define CP_ASYNC16(saddr, gptr) \
    asm volatile("cp.async.cg.shared.global [%0], [%1], 16;" :: "r"(saddr), "l"(gptr))

// ---------------- split-bf16 tensor-core GEMM (mma.sync path, no tcgen05) ----------------
// C[M,N] = A[M,K] * B[N,K]^T in split precision:
//   C = Ahi*Bhi + Alo*Bhi + Ahi*Blo   (three K-segments, one fp32 accumulator)
// Tile: 128x128, BK=64 bf16 (128B rows, SW128 swizzle), 256 threads (4x2 warps),
// cp.async double buffering.
#define GBM 128
#define GBN 128
#define GKC 64
#define STAGE_BYTES 32768           // 16KB A + 16KB B
#define GSMEM (2*STAGE_BYTES + 1024)

__global__ void __launch_bounds__(256, 1) gemm_mma_bf16x3(
    const __nv_bfloat16* __restrict__ Ahi, const __nv_bfloat16* __restrict__ Alo,
    const __nv_bfloat16* __restrict__ Bhi, const __nv_bfloat16* __restrict__ Blo,
    float* __restrict__ C, int M, int N, int K)
{
    extern __shared__ char dsm[];
    const int tid = threadIdx.x;
    const int wid = tid >> 5, lane = tid & 31;
    const int bm = blockIdx.y * GBM, bn = blockIdx.x * GBN;
    const int m0 = (wid & 3) * 32;       // warp row block
    const int n0 = (wid >> 2) * 64;      // warp col block

    uint32_t raw = smem_u32(dsm);
    uint32_t base = (raw + 1023u) & ~1023u;

    const int segC = K / GKC;            // chunks per segment
    const int NC = 3 * segC;             // total chunks

    float acc[2][8][4];
#pragma unroll
    for (int i = 0; i < 2; i++)
#pragma unroll
        for (int j = 0; j < 8; j++)
#pragma unroll
            for (int q = 0; q < 4; q++) acc[i][j][q] = 0.f;

    // cp.async issue of one chunk into stage buf
    auto issue = [&](int c, int buf) {
        int seg = c / segC;
        int kc = (c - seg * segC) * GKC;
        const __nv_bfloat16* Ag = (seg == 1) ? Alo : Ahi;
        const __nv_bfloat16* Bg = (seg == 2) ? Blo : Bhi;
        uint32_t abase = base + (uint32_t)buf * STAGE_BYTES;
        uint32_t bbase = abase + 16384u;
#pragma unroll
        for (int i = 0; i < 4; i++) {
            int idx = tid + i * 256;
            int r = idx >> 3, q = idx & 7;
            uint32_t off = (uint32_t)(r * 128 + q * 16);
            uint32_t swo = off ^ ((off >> 3) & 0x70u);
            CP_ASYNC16(abase + swo, Ag + (size_t)(bm + r) * K + kc + q * 8);
            CP_ASYNC16(bbase + swo, Bg + (size_t)(bn + r) * K + kc + q * 8);
        }
        asm volatile("cp.async.commit_group;" ::: "memory");
    };

    issue(0, 0);

    for (int c = 0; c < NC; c++) {
        const int buf = c & 1;
        if (c + 1 < NC) {
            issue(c + 1, (c + 1) & 1);
            asm volatile("cp.async.wait_group 1;" ::: "memory");
        } else {
            asm volatile("cp.async.wait_group 0;" ::: "memory");
        }
        __syncthreads();

        uint32_t abase = base + (uint32_t)buf * STAGE_BYTES;
        uint32_t bbase = abase + 16384u;
#pragma unroll
        for (int ks = 0; ks < 4; ks++) {
            uint32_t a[2][4];
#pragma unroll
            for (int mt = 0; mt < 2; mt++) {
                int row = m0 + mt * 16 + (lane & 15);
                int kb = ks * 16 + ((lane >> 4) << 3);
                uint32_t off = (uint32_t)(row * 128 + kb * 2);
                uint32_t ad = abase + (off ^ ((off >> 3) & 0x70u));
                LDSM_X4(a[mt][0], a[mt][1], a[mt][2], a[mt][3], ad);
            }
            uint32_t b[4][4];
#pragma unroll
            for (int np = 0; np < 4; np++) {
                int nr = n0 + np * 16 + (lane & 7) + ((lane >> 4) << 3);
                int kb = ks * 16 + (((lane >> 3) & 1) << 3);
                uint32_t off = (uint32_t)(nr * 128 + kb * 2);
                uint32_t ad = bbase + (off ^ ((off >> 3) & 0x70u));
                LDSM_X4(b[np][0], b[np][1], b[np][2], b[np][3], ad);
            }
#pragma unroll
            for (int mt = 0; mt < 2; mt++)
#pragma unroll
                for (int np = 0; np < 4; np++) {
                    mma16816(acc[mt][np * 2 + 0], a[mt], b[np][0], b[np][1]);
                    mma16816(acc[mt][np * 2 + 1], a[mt], b[np][2], b[np][3]);
                }
        }
        __syncthreads();
    }

    // epilogue
#pragma unroll
    for (int mt = 0; mt < 2; mt++) {
        int row = bm + m0 + mt * 16 + (lane >> 2);
#pragma unroll
        for (int nt = 0; nt < 8; nt++) {
            int col = bn + n0 + nt * 8 + (lane & 3) * 2;
            *(float2*)&C[(size_t)row * N + col] = make_float2(acc[mt][nt][0], acc[mt][nt][1]);
            *(float2*)&C[(size_t)(row + 8) * N + col] = make_float2(acc[mt][nt][2], acc[mt][nt][3]);
        }
    }
}

// ---------------- fp32 -> split-bf16 conversions ----------------
__global__ void cvt_act(const float* __restrict__ x, __nv_bfloat16* __restrict__ hi,
                        __nv_bfloat16* __restrict__ lo, size_t n)
{
    size_t i = (size_t)blockIdx.x * blockDim.x + threadIdx.x;
    if (i < n) {
        float v = x[i];
        __nv_bfloat16 h = __float2bfloat16(v);
        hi[i] = h;
        lo[i] = __float2bfloat16(v - __bfloat162float(h));
    }
}
// weights: W[K,N] row-major -> B[N,K] (transposed) split
__global__ void cvt_wt_t(const float* __restrict__ w, __nv_bfloat16* __restrict__ bhi,
                         __nv_bfloat16* __restrict__ blo, int K, int N)
{
    __shared__ float t[32][33];
    int k0 = blockIdx.y * 32, n0 = blockIdx.x * 32;
    int tx = threadIdx.x, ty = threadIdx.y;  // 32 x 8
    #pragma unroll
    for (int i = 0; i < 32; i += 8)
        t[ty + i][tx] = w[(size_t)(k0 + ty + i) * N + n0 + tx];
    __syncthreads();
    #pragma unroll
    for (int i = 0; i < 32; i += 8) {
        float v = t[tx][ty + i];   // = w[k0+tx][n0+ty+i]
        __nv_bfloat16 h = __float2bfloat16(v);
        size_t o = (size_t)(n0 + ty + i) * K + k0 + tx;
        bhi[o] = h;
        blo[o] = __float2bfloat16(v - __bfloat162float(h));
    }
}

// ---------------- LayerNorm (biased var, no bias), optional fused residual ----------------
__global__ void ln_kernel(const float* __restrict__ in, const float* __restrict__ g,
                          const float* __restrict__ res, float* __restrict__ out, int D)
{
    int row = blockIdx.x;
    const float* x = in + (size_t)row * D;
    float s = 0.f, sq = 0.f;
    for (int c = threadIdx.x; c < D; c += blockDim.x) { float v = x[c]; s += v; sq += v*v; }
    __shared__ float sh[64];
    for (int o = 16; o; o >>= 1) { s += __shfl_xor_sync(0xffffffffu, s, o); sq += __shfl_xor_sync(0xffffffffu, sq, o); }
    int wid = threadIdx.x >> 5, lid = threadIdx.x & 31;
    if (lid == 0) { sh[wid] = s; sh[wid + 32] = sq; }
    __syncthreads();
    if (wid == 0) {
        int nw = blockDim.x >> 5;
        float a = (lid < nw) ? sh[lid] : 0.f;
        float b = (lid < nw) ? sh[lid + 32] : 0.f;
        for (int o = 16; o; o >>= 1) { a += __shfl_xor_sync(0xffffffffu, a, o); b += __shfl_xor_sync(0xffffffffu, b, o); }
        if (lid == 0) { sh[0] = a; sh[1] = b; }
    }
    __syncthreads();
    float mean = sh[0] / D;
    float var  = sh[1] / D - mean * mean;
    float rstd = rsqrtf(var + 1e-5f);
    float* o = out + (size_t)row * D;
    const float* rr = res ? res + (size_t)row * D : nullptr;
    for (int c = threadIdx.x; c < D; c += blockDim.x) {
        float v = (x[c] - mean) * rstd * g[c];
        if (rr) v += rr[c];
        o[c] = v;
    }
}

// ---------------- attention: S = scale * Q K^T (per b,h), 64x64 tiles, skip masked tiles ----------------
__global__ void qk_kernel(const float* __restrict__ qkv, float* __restrict__ S)
{
    int bh = blockIdx.z; int b = bh >> 4, h = bh & 15;
    int jt = blockIdx.x, it = blockIdx.y;
    if (jt > it) return;  // fully masked tile; softmax writes zeros there
    __shared__ float Qs[64][68];
    __shared__ float Ks[64][68];
    int tid = threadIdx.x;
    const float* qbase = qkv + (size_t)(b * SEQ + it * 64) * (3 * DMODEL) + h * DHEAD;
    const float* kbase = qkv + (size_t)(b * SEQ + jt * 64) * (3 * DMODEL) + DMODEL + h * DHEAD;
#pragma unroll
    for (int idx = tid; idx < 64 * 16; idx += 256) {
        int r = idx / 16, c4 = idx % 16;
        *(float4*)&Qs[r][c4 * 4] = *(const float4*)(qbase + (size_t)r * (3 * DMODEL) + c4 * 4);
        *(float4*)&Ks[r][c4 * 4] = *(const float4*)(kbase + (size_t)r * (3 * DMODEL) + c4 * 4);
    }
    __syncthreads();
    int tx = tid & 15, ty = tid >> 4;
    float acc[4][4] = {};
#pragma unroll
    for (int d = 0; d < 64; d++) {
        float a[4], bb[4];
#pragma unroll
        for (int i = 0; i < 4; i++) a[i] = Qs[ty * 4 + i][d];
#pragma unroll
        for (int j = 0; j < 4; j++) bb[j] = Ks[tx * 4 + j][d];
#pragma unroll
        for (int i = 0; i < 4; i++)
#pragma unroll
            for (int j = 0; j < 4; j++) acc[i][j] += a[i] * bb[j];
    }
    const float scale = 0.125f; // DHEAD^-0.5
    float* srow = S + ((size_t)bh << 20) + (size_t)(it * 64) * SEQ + jt * 64;
#pragma unroll
    for (int i = 0; i < 4; i++)
#pragma unroll
        for (int j = 0; j < 4; j++)
            srow[(size_t)(ty * 4 + i) * SEQ + tx * 4 + j] = acc[i][j] * scale;
}

// ---------------- row softmax over valid prefix j<=i, zeros elsewhere ----------------
__global__ void softmax_kernel(float* __restrict__ S)
{
    int row = blockIdx.x;            // bh*1024 + i
    int i = row & (SEQ - 1);
    float* p = S + (size_t)row * SEQ;
    int L = i + 1;
    int tid = threadIdx.x;
    __shared__ float sh[32];
    float m = -3.4028235e38f;
    for (int j = tid; j < L; j += 256) m = fmaxf(m, p[j]);
    for (int o = 16; o; o >>= 1) m = fmaxf(m, __shfl_xor_sync(0xffffffffu, m, o));
    if ((tid & 31) == 0) sh[tid >> 5] = m;
    __syncthreads();
    if (tid < 32) {
        float v = (tid < 8) ? sh[tid] : -3.4028235e38f;
        for (int o = 4; o; o >>= 1) v = fmaxf(v, __shfl_xor_sync(0xffffffffu, v, o));
        if (tid == 0) sh[0] = v;
    }
    __syncthreads();
    m = sh[0];
    __syncthreads();
    float s = 0.f;
    for (int j = tid; j < L; j += 256) { float e = expf(p[j] - m); p[j] = e; s += e; }
    for (int o = 16; o; o >>= 1) s += __shfl_xor_sync(0xffffffffu, s, o);
    if ((tid & 31) == 0) sh[tid >> 5] = s;
    __syncthreads();
    if (tid < 32) {
        float v = (tid < 8) ? sh[tid] : 0.f;
        for (int o = 4; o; o >>= 1) v += __shfl_xor_sync(0xffffffffu, v, o);
        if (tid == 0) sh[0] = v;
    }
    __syncthreads();
    float inv = 1.0f / sh[0];
    for (int j = tid; j < L; j += 256) p[j] *= inv;
    for (int j = L + tid; j < SEQ; j += 256) p[j] = 0.f;
}

// ---------------- O = P @ V (per b,h), causal-truncated K-loop, writes merged-head layout ----------------
__global__ void pv_kernel(const float* __restrict__ S, const float* __restrict__ qkv,
                          float* __restrict__ out)
{
    int it = blockIdx.x;   // 16 query tiles of 64
    int bh = blockIdx.y;   // 64
    int b = bh >> 4, h = bh & 15;
    __shared__ float Ps[64][36];
    __shared__ float Vs[32][68];
    int tid = threadIdx.x;
    int tx = tid & 15, ty = tid >> 4;
    const float* sbase = S + ((size_t)bh << 20) + (size_t)(it * 64) * SEQ;
    const float* vbase = qkv + 2 * DMODEL + h * DHEAD;
    float acc[4][4] = {};
    int kend = (it + 1) * 64;
    for (int j0 = 0; j0 < kend; j0 += 32) {
#pragma unroll
        for (int idx = tid; idx < 64 * 8; idx += 256) {
            int r = idx / 8, c4 = idx % 8;
            *(float4*)&Ps[r][c4 * 4] = *(const float4*)(sbase + (size_t)r * SEQ + j0 + c4 * 4);
        }
#pragma unroll
        for (int idx = tid; idx < 32 * 16; idx += 256) {
            int r = idx / 16, c4 = idx % 16;
            *(float4*)&Vs[r][c4 * 4] =
                *(const float4*)(vbase + (size_t)(b * SEQ + j0 + r) * (3 * DMODEL) + c4 * 4);
        }
        __syncthreads();
#pragma unroll
        for (int jj = 0; jj < 32; jj++) {
            float a[4], vv[4];
#pragma unroll
            for (int i = 0; i < 4; i++) a[i] = Ps[ty * 4 + i][jj];
#pragma unroll
            for (int d = 0; d < 4; d++) vv[d] = Vs[jj][tx * 4 + d];
#pragma unroll
            for (int i = 0; i < 4; i++)
#pragma unroll
                for (int d = 0; d < 4; d++) acc[i][d] += a[i] * vv[d];
        }
        __syncthreads();
    }
#pragma unroll
    for (int i = 0; i < 4; i++) {
        size_t row = (size_t)(b * SEQ + it * 64 + ty * 4 + i) * DMODEL + h * DHEAD + tx * 4;
#pragma unroll
        for (int d = 0; d < 4; d++) out[row + d] = acc[i][d];
    }
}

// ---------------- GEGLU: o = a * gelu_exact(gate) ----------------
__global__ void geglu_kernel(const float* __restrict__ h, float* __restrict__ o)
{
    int idx = blockIdx.x * blockDim.x + threadIdx.x;   // < 4096*4096
    int m = idx >> 12, c = idx & 4095;
    float a = h[(size_t)m * (2 * FFI) + c];
    float g = h[(size_t)m * (2 * FFI) + FFI + c];
    float ge = 0.5f * g * (1.0f + erff(g * 0.70710678118654752f));
    o[idx] = a * ge;
}

__global__ void add_kernel(float* __restrict__ x, const float* __restrict__ y, int n)
{
    int i = blockIdx.x * blockDim.x + threadIdx.x;
    if (i < n) x[i] += y[i];
}

// ---------------- host-side GEMM wrapper ----------------
static void tc_gemm(const float* A, const float* W, float* C, int M, int N, int K,
                    __nv_bfloat16* ahi, __nv_bfloat16* alo,
                    __nv_bfloat16* bhi, __nv_bfloat16* blo)
{
    size_t na = (size_t)M * K;
    cvt_act<<<(unsigned)((na + 255) / 256), 256>>>(A, ahi, alo, na);
    cvt_wt_t<<<dim3(N / 32, K / 32), dim3(32, 8)>>>(W, bhi, blo, K, N);
    gemm_mma_bf16x3<<<dim3(N / GBN, M / GBM), 256, GSMEM>>>(ahi, alo, bhi, blo, C, M, N, K);
}

// ---------------- orchestration ----------------
extern "C" void kernel_launch(void* const* d_in, const int* in_sizes, int n_in,
                              void* d_out, int out_size)
{
    const float* x_in   = (const float*)d_in[0];
    const float* qkv_w  = (const float*)d_in[1];
    const float* out_w  = (const float*)d_in[2];
    const float* ff_w1  = (const float*)d_in[3];
    const float* ff_w2  = (const float*)d_in[4];
    const float* attn_g = (const float*)d_in[5];
    const float* outln_g= (const float*)d_in[6];
    const float* ffn_g  = (const float*)d_in[7];
    const float* ffln_g = (const float*)d_in[8];
    const float* nin_g  = (const float*)d_in[9];
    const float* nout_g = (const float*)d_in[10];
    float* out = (float*)d_out;

    float *xbuf, *lnbuf, *qkvb, *Sb, *attno, *proj, *ff1, *geg, *ffln;
    __nv_bfloat16 *ahi, *alo, *bhi, *blo;
    cudaGetSymbolAddress((void**)&xbuf,  g_xbuf);
    cudaGetSymbolAddress((void**)&lnbuf, g_lnbuf);
    cudaGetSymbolAddress((void**)&qkvb,  g_qkv);
    cudaGetSymbolAddress((void**)&Sb,    g_S);
    cudaGetSymbolAddress((void**)&attno, g_attno);
    cudaGetSymbolAddress((void**)&proj,  g_proj);
    cudaGetSymbolAddress((void**)&ff1,   g_ff1);
    cudaGetSymbolAddress((void**)&geg,   g_geglu);
    cudaGetSymbolAddress((void**)&ffln,  g_ffln);
    cudaGetSymbolAddress((void**)&ahi,   g_ahi);
    cudaGetSymbolAddress((void**)&alo,   g_alo);
    cudaGetSymbolAddress((void**)&bhi,   g_bhi);
    cudaGetSymbolAddress((void**)&blo,   g_blo);

    cudaFuncSetAttribute(gemm_mma_bf16x3, cudaFuncAttributeMaxDynamicSharedMemorySize, GSMEM);

    const int M = MROWS;
    // x = LN(x, norm_in_g)
    ln_kernel<<<M, 256>>>(x_in, nin_g, nullptr, xbuf, DMODEL);

    for (int l = 0; l < NDEPTH; l++) {
        // ---- attention block ----
        ln_kernel<<<M, 256>>>(xbuf, attn_g + (size_t)l * DMODEL, nullptr, lnbuf, DMODEL);
        tc_gemm(lnbuf, qkv_w + (size_t)l * DMODEL * 3 * DMODEL, qkvb,
                M, 3 * DMODEL, DMODEL, ahi, alo, bhi, blo);
        qk_kernel<<<dim3(16, 16, BH), 256>>>(qkvb, Sb);
        softmax_kernel<<<BH * SEQ, 256>>>(Sb);
        pv_kernel<<<dim3(16, BH), 256>>>(Sb, qkvb, attno);
        tc_gemm(attno, out_w + (size_t)l * DMODEL * DMODEL, proj,
                M, DMODEL, DMODEL, ahi, alo, bhi, blo);
        // x = LN(proj, out_ln_g) + x
        ln_kernel<<<M, 256>>>(proj, outln_g + (size_t)l * DMODEL, xbuf, xbuf, DMODEL);

        // ---- GEGLU feedforward ----
        ln_kernel<<<M, 256>>>(xbuf, ffn_g + (size_t)l * DMODEL, nullptr, lnbuf, DMODEL);
        tc_gemm(lnbuf, ff_w1 + (size_t)l * DMODEL * 2 * FFI, ff1,
                M, 2 * FFI, DMODEL, ahi, alo, bhi, blo);
        geglu_kernel<<<(M * FFI) / 256, 256>>>(ff1, geg);
        ln_kernel<<<M, 256>>>(geg, ffln_g + (size_t)l * FFI, nullptr, ffln, FFI);
        tc_gemm(ffln, ff_w2 + (size_t)l * FFI * DMODEL, proj,
                M, DMODEL, FFI, ahi, alo, bhi, blo);
        add_kernel<<<(M * DMODEL) / 256, 256>>>(xbuf, proj, M * DMODEL);
    }
    // out = LN(x, norm_out_g)
    ln_kernel<<<M, 256>>>(xbuf, nout_g, nullptr, out, DMODEL);
}

// round 5
// speedup vs baseline: 3.1118x; 1.2232x over previous
#include <cuda_runtime.h>
#include <cuda_bf16.h>
#include <math.h>
#include <stdint.h>

typedef unsigned long long ull;

// ---------------- model dims ----------------
#define NDEPTH 6
#define DMODEL 1024
#define NHEADS 16
#define DHEAD  64
#define SEQ    1024
#define BATCH  4
#define MROWS  (BATCH*SEQ)        // 4096
#define FFI    4096               // FF_INNER
#define BH     (BATCH*NHEADS)     // 64

// ---------------- scratch (static device memory; no allocs allowed) ----------------
__device__ float g_xbuf [MROWS*DMODEL];
__device__ float g_S    [(size_t)BH*SEQ*SEQ];     // fp32 scores
__device__ float g_proj [MROWS*DMODEL];
__device__ float g_ff1  [(size_t)MROWS*2*FFI];
__device__ float g_geglu[(size_t)MROWS*FFI];

__device__ __nv_bfloat16 g_ahi[(size_t)MROWS*FFI];       // GEMM A operand (split)
__device__ __nv_bfloat16 g_alo[(size_t)MROWS*FFI];
__device__ __nv_bfloat16 g_bhi[(size_t)(2*FFI)*DMODEL];  // weights [N,K] split
__device__ __nv_bfloat16 g_blo[(size_t)(2*FFI)*DMODEL];
__device__ __nv_bfloat16 g_qkvhi[(size_t)MROWS*3*DMODEL];
__device__ __nv_bfloat16 g_qkvlo[(size_t)MROWS*3*DMODEL];
__device__ __nv_bfloat16 g_phi[(size_t)BH*SEQ*SEQ];      // probs split
__device__ __nv_bfloat16 g_plo[(size_t)BH*SEQ*SEQ];

// ---------------- helpers ----------------
__device__ __forceinline__ uint32_t smem_u32(const void* p) {
    uint32_t a;
    asm("{ .reg .u64 t; cvta.to.shared.u64 t, %1; cvt.u32.u64 %0, t; }" : "=r"(a) : "l"(p));
    return a;
}
__device__ __forceinline__ void mma16816(float* c, const uint32_t* a, uint32_t b0, uint32_t b1) {
    asm volatile(
        "mma.sync.aligned.m16n8k16.row.col.f32.bf16.bf16.f32 "
        "{%0,%1,%2,%3}, {%4,%5,%6,%7}, {%8,%9}, {%0,%1,%2,%3};"
        : "+f"(c[0]), "+f"(c[1]), "+f"(c[2]), "+f"(c[3])
        : "r"(a[0]), "r"(a[1]), "r"(a[2]), "r"(a[3]), "r"(b0), "r"(b1));
}
#define LDSM_X4(r0, r1, r2, r3, addr) \
    asm volatile("ldmatrix.sync.aligned.m8n8.x4.shared.b16 {%0,%1,%2,%3}, [%4];" \
                 : "=r"(r0), "=r"(r1), "=r"(r2), "=r"(r3) : "r"(addr))
#define LDSM_X4_T(r0, r1, r2, r3, addr) \
    asm volatile("ldmatrix.sync.aligned.m8n8.x4.trans.shared.b16 {%0,%1,%2,%3}, [%4];" \
                 : "=r"(r0), "=r"(r1), "=r"(r2), "=r"(r3) : "r"(addr))
#define CP_ASYNC16(saddr, gptr) \
    asm volatile("cp.async.cg.shared.global [%0], [%1], 16;" :: "r"(saddr), "l"(gptr))
__device__ __forceinline__ uint32_t sw128(uint32_t off) { return off ^ ((off >> 3) & 0x70u); }
__device__ __forceinline__ void split2(float v, __nv_bfloat16& h, __nv_bfloat16& l) {
    h = __float2bfloat16(v);
    l = __float2bfloat16(v - __bfloat162float(h));
}

// ---------------- split-bf16 tensor-core GEMM ----------------
// C = Ahi*Bhi + Alo*Bhi + Ahi*Blo  (three K-segments, one fp32 accumulator)
// Epilogue modes: split-bf16 out (Chi/Clo), fp32 + residual, plain fp32.
#define GBM 128
#define GBN 128
#define GKC 64
#define STAGE_BYTES 32768
#define GSMEM (2*STAGE_BYTES + 1024)

__global__ void __launch_bounds__(256, 1) gemm_mma_bf16x3(
    const __nv_bfloat16* __restrict__ Ahi, const __nv_bfloat16* __restrict__ Alo,
    const __nv_bfloat16* __restrict__ Bhi, const __nv_bfloat16* __restrict__ Blo,
    float* __restrict__ C, __nv_bfloat16* __restrict__ Chi, __nv_bfloat16* __restrict__ Clo,
    const float* __restrict__ resid, int M, int N, int K)
{
    extern __shared__ char dsm[];
    const int tid = threadIdx.x;
    const int wid = tid >> 5, lane = tid & 31;
    const int bm = blockIdx.y * GBM, bn = blockIdx.x * GBN;
    const int m0 = (wid & 3) * 32;
    const int n0 = (wid >> 2) * 64;

    uint32_t raw = smem_u32(dsm);
    uint32_t base = (raw + 1023u) & ~1023u;

    const int segC = K / GKC;
    const int NC = 3 * segC;

    float acc[2][8][4];
#pragma unroll
    for (int i = 0; i < 2; i++)
#pragma unroll
        for (int j = 0; j < 8; j++)
#pragma unroll
            for (int q = 0; q < 4; q++) acc[i][j][q] = 0.f;

    auto issue = [&](int c, int buf) {
        int seg = c / segC;
        int kc = (c - seg * segC) * GKC;
        const __nv_bfloat16* Ag = (seg == 1) ? Alo : Ahi;
        const __nv_bfloat16* Bg = (seg == 2) ? Blo : Bhi;
        uint32_t abase = base + (uint32_t)buf * STAGE_BYTES;
        uint32_t bbase = abase + 16384u;
#pragma unroll
        for (int i = 0; i < 4; i++) {
            int idx = tid + i * 256;
            int r = idx >> 3, q = idx & 7;
            uint32_t swo = sw128((uint32_t)(r * 128 + q * 16));
            CP_ASYNC16(abase + swo, Ag + (size_t)(bm + r) * K + kc + q * 8);
            CP_ASYNC16(bbase + swo, Bg + (size_t)(bn + r) * K + kc + q * 8);
        }
        asm volatile("cp.async.commit_group;" ::: "memory");
    };

    issue(0, 0);

    for (int c = 0; c < NC; c++) {
        const int buf = c & 1;
        if (c + 1 < NC) {
            issue(c + 1, (c + 1) & 1);
            asm volatile("cp.async.wait_group 1;" ::: "memory");
        } else {
            asm volatile("cp.async.wait_group 0;" ::: "memory");
        }
        __syncthreads();

        uint32_t abase = base + (uint32_t)buf * STAGE_BYTES;
        uint32_t bbase = abase + 16384u;
#pragma unroll
        for (int ks = 0; ks < 4; ks++) {
            uint32_t a[2][4];
#pragma unroll
            for (int mt = 0; mt < 2; mt++) {
                int row = m0 + mt * 16 + (lane & 15);
                int kb = ks * 16 + ((lane >> 4) << 3);
                uint32_t ad = abase + sw128((uint32_t)(row * 128 + kb * 2));
                LDSM_X4(a[mt][0], a[mt][1], a[mt][2], a[mt][3], ad);
            }
            uint32_t b[4][4];
#pragma unroll
            for (int np = 0; np < 4; np++) {
                int nr = n0 + np * 16 + (lane & 7) + ((lane >> 4) << 3);
                int kb = ks * 16 + (((lane >> 3) & 1) << 3);
                uint32_t ad = bbase + sw128((uint32_t)(nr * 128 + kb * 2));
                LDSM_X4(b[np][0], b[np][1], b[np][2], b[np][3], ad);
            }
#pragma unroll
            for (int mt = 0; mt < 2; mt++)
#pragma unroll
                for (int np = 0; np < 4; np++) {
                    mma16816(acc[mt][np * 2 + 0], a[mt], b[np][0], b[np][1]);
                    mma16816(acc[mt][np * 2 + 1], a[mt], b[np][2], b[np][3]);
                }
        }
        __syncthreads();
    }

    // epilogue
#pragma unroll
    for (int mt = 0; mt < 2; mt++) {
        int row = bm + m0 + mt * 16 + (lane >> 2);
#pragma unroll
        for (int nt = 0; nt < 8; nt++) {
            int col = bn + n0 + nt * 8 + (lane & 3) * 2;
            size_t i0 = (size_t)row * N + col;
            size_t i1 = (size_t)(row + 8) * N + col;
            if (Chi) {
                __nv_bfloat162 h2, l2;
                split2(acc[mt][nt][0], h2.x, l2.x);
                split2(acc[mt][nt][1], h2.y, l2.y);
                *(__nv_bfloat162*)&Chi[i0] = h2;
                *(__nv_bfloat162*)&Clo[i0] = l2;
                split2(acc[mt][nt][2], h2.x, l2.x);
                split2(acc[mt][nt][3], h2.y, l2.y);
                *(__nv_bfloat162*)&Chi[i1] = h2;
                *(__nv_bfloat162*)&Clo[i1] = l2;
            } else if (resid) {
                float2 r0 = *(const float2*)&resid[i0];
                float2 r1 = *(const float2*)&resid[i1];
                *(float2*)&C[i0] = make_float2(acc[mt][nt][0] + r0.x, acc[mt][nt][1] + r0.y);
                *(float2*)&C[i1] = make_float2(acc[mt][nt][2] + r1.x, acc[mt][nt][3] + r1.y);
            } else {
                *(float2*)&C[i0] = make_float2(acc[mt][nt][0], acc[mt][nt][1]);
                *(float2*)&C[i1] = make_float2(acc[mt][nt][2], acc[mt][nt][3]);
            }
        }
    }
}

// ---------------- weights: W[K,N] row-major -> B[N,K] transposed split ----------------
__global__ void cvt_wt_t(const float* __restrict__ w, __nv_bfloat16* __restrict__ bhi,
                         __nv_bfloat16* __restrict__ blo, int K, int N)
{
    __shared__ float t[32][33];
    int k0 = blockIdx.y * 32, n0 = blockIdx.x * 32;
    int tx = threadIdx.x, ty = threadIdx.y;  // 32 x 8
    #pragma unroll
    for (int i = 0; i < 32; i += 8)
        t[ty + i][tx] = w[(size_t)(k0 + ty + i) * N + n0 + tx];
    __syncthreads();
    #pragma unroll
    for (int i = 0; i < 32; i += 8) {
        float v = t[tx][ty + i];
        __nv_bfloat16 h, l;
        split2(v, h, l);
        size_t o = (size_t)(n0 + ty + i) * K + k0 + tx;
        bhi[o] = h;
        blo[o] = l;
    }
}

// ---------------- LayerNorm variants ----------------
__device__ __forceinline__ void ln_stats(const float* x, int D, int tid, float& mean, float& rstd)
{
    float s = 0.f, sq = 0.f;
    for (int c = tid; c < D; c += 256) { float v = x[c]; s += v; sq += v * v; }
    __shared__ float sh[64];
    for (int o = 16; o; o >>= 1) { s += __shfl_xor_sync(0xffffffffu, s, o); sq += __shfl_xor_sync(0xffffffffu, sq, o); }
    int wid = tid >> 5, lid = tid & 31;
    if (lid == 0) { sh[wid] = s; sh[wid + 32] = sq; }
    __syncthreads();
    if (wid == 0) {
        float a = (lid < 8) ? sh[lid] : 0.f;
        float b = (lid < 8) ? sh[lid + 32] : 0.f;
        for (int o = 4; o; o >>= 1) { a += __shfl_xor_sync(0xffffffffu, a, o); b += __shfl_xor_sync(0xffffffffu, b, o); }
        if (lid == 0) { sh[0] = a; sh[1] = b; }
    }
    __syncthreads();
    mean = sh[0] / D;
    float var = sh[1] / D - mean * mean;
    rstd = rsqrtf(var + 1e-5f);
}

// fp32 out, optional residual
__global__ void ln_kernel(const float* __restrict__ in, const float* __restrict__ g,
                          const float* __restrict__ res, float* __restrict__ out, int D)
{
    int row = blockIdx.x;
    const float* x = in + (size_t)row * D;
    float mean, rstd;
    ln_stats(x, D, threadIdx.x, mean, rstd);
    float* o = out + (size_t)row * D;
    const float* rr = res ? res + (size_t)row * D : nullptr;
    for (int c = threadIdx.x; c < D; c += 256) {
        float v = (x[c] - mean) * rstd * g[c];
        if (rr) v += rr[c];
        o[c] = v;
    }
}

// split-bf16 out (GEMM A operand)
__global__ void ln_split(const float* __restrict__ in, const float* __restrict__ g,
                         __nv_bfloat16* __restrict__ hi, __nv_bfloat16* __restrict__ lo, int D)
{
    int row = blockIdx.x;
    const float* x = in + (size_t)row * D;
    float mean, rstd;
    ln_stats(x, D, threadIdx.x, mean, rstd);
    for (int c = threadIdx.x; c < D; c += 256) {
        float v = (x[c] - mean) * rstd * g[c];
        __nv_bfloat16 h, l;
        split2(v, h, l);
        hi[(size_t)row * D + c] = h;
        lo[(size_t)row * D + c] = l;
    }
}

// ---------------- tensorized QK^T: S = 0.125 * Q K^T, 64x64 tiles, split-bf16 ----------------
__global__ void __launch_bounds__(128) qk_mma(
    const __nv_bfloat16* __restrict__ qkvhi, const __nv_bfloat16* __restrict__ qkvlo,
    float* __restrict__ S)
{
    int bh = blockIdx.z; int b = bh >> 4, h = bh & 15;
    int jt = blockIdx.x, it = blockIdx.y;
    if (jt > it) return;

    __shared__ char sm[32768];   // Qhi 0, Qlo 8K, Khi 16K, Klo 24K
    uint32_t sb = smem_u32(sm);
    const int tid = threadIdx.x;
    const int wid = tid >> 5, lane = tid & 31;
    const int wm = (wid & 1) * 32, wn = (wid >> 1) * 32;

    const size_t qrow = (size_t)(b * SEQ + it * 64) * (3 * DMODEL) + h * DHEAD;
    const size_t krow = (size_t)(b * SEQ + jt * 64) * (3 * DMODEL) + DMODEL + h * DHEAD;
#pragma unroll
    for (int i = 0; i < 4; i++) {
        int idx = tid + i * 128;
        int r = idx >> 3, q = idx & 7;
        uint32_t swo = sw128((uint32_t)(r * 128 + q * 16));
        size_t qo = qrow + (size_t)r * (3 * DMODEL) + q * 8;
        size_t ko = krow + (size_t)r * (3 * DMODEL) + q * 8;
        *(uint4*)(sm + swo)          = *(const uint4*)(qkvhi + qo);
        *(uint4*)(sm + 8192 + swo)   = *(const uint4*)(qkvlo + qo);
        *(uint4*)(sm + 16384 + swo)  = *(const uint4*)(qkvhi + ko);
        *(uint4*)(sm + 24576 + swo)  = *(const uint4*)(qkvlo + ko);
    }
    __syncthreads();

    float acc[2][4][4];
#pragma unroll
    for (int i = 0; i < 2; i++)
#pragma unroll
        for (int j = 0; j < 4; j++)
#pragma unroll
            for (int q = 0; q < 4; q++) acc[i][j][q] = 0.f;

#pragma unroll
    for (int ks = 0; ks < 4; ks++) {
        uint32_t ah[2][4], al[2][4];
#pragma unroll
        for (int mt = 0; mt < 2; mt++) {
            int row = wm + mt * 16 + (lane & 15);
            int kb = ks * 16 + ((lane >> 4) << 3);
            uint32_t swo = sw128((uint32_t)(row * 128 + kb * 2));
            LDSM_X4(ah[mt][0], ah[mt][1], ah[mt][2], ah[mt][3], sb + swo);
            LDSM_X4(al[mt][0], al[mt][1], al[mt][2], al[mt][3], sb + 8192 + swo);
        }
        uint32_t bfh[2][4], bfl[2][4];
#pragma unroll
        for (int np = 0; np < 2; np++) {
            int nr = wn + np * 16 + (lane & 7) + ((lane >> 4) << 3);
            int kb = ks * 16 + (((lane >> 3) & 1) << 3);
            uint32_t swo = sw128((uint32_t)(nr * 128 + kb * 2));
            LDSM_X4(bfh[np][0], bfh[np][1], bfh[np][2], bfh[np][3], sb + 16384 + swo);
            LDSM_X4(bfl[np][0], bfl[np][1], bfl[np][2], bfl[np][3], sb + 24576 + swo);
        }
#pragma unroll
        for (int mt = 0; mt < 2; mt++)
#pragma unroll
            for (int np = 0; np < 2; np++) {
                mma16816(acc[mt][np * 2 + 0], ah[mt], bfh[np][0], bfh[np][1]);
                mma16816(acc[mt][np * 2 + 0], ah[mt], bfl[np][0], bfl[np][1]);
                mma16816(acc[mt][np * 2 + 0], al[mt], bfh[np][0], bfh[np][1]);
                mma16816(acc[mt][np * 2 + 1], ah[mt], bfh[np][2], bfh[np][3]);
                mma16816(acc[mt][np * 2 + 1], ah[mt], bfl[np][2], bfl[np][3]);
                mma16816(acc[mt][np * 2 + 1], al[mt], bfh[np][2], bfh[np][3]);
            }
    }

    const float scale = 0.125f;
    float* sbase = S + ((size_t)bh << 20);
#pragma unroll
    for (int mt = 0; mt < 2; mt++) {
        int row = it * 64 + wm + mt * 16 + (lane >> 2);
#pragma unroll
        for (int nt = 0; nt < 4; nt++) {
            int col = jt * 64 + wn + nt * 8 + (lane & 3) * 2;
            *(float2*)&sbase[(size_t)row * SEQ + col] =
                make_float2(acc[mt][nt][0] * scale, acc[mt][nt][1] * scale);
            *(float2*)&sbase[(size_t)(row + 8) * SEQ + col] =
                make_float2(acc[mt][nt][2] * scale, acc[mt][nt][3] * scale);
        }
    }
}

// ---------------- row softmax -> split-bf16 P (single global read of S) ----------------
__global__ void softmax_split(const float* __restrict__ S,
                              __nv_bfloat16* __restrict__ phi, __nv_bfloat16* __restrict__ plo)
{
    int row = blockIdx.x;            // bh*1024 + i
    int i = row & (SEQ - 1);
    const float* p = S + (size_t)row * SEQ;
    int L = i + 1;
    int tid = threadIdx.x;
    __shared__ float sh[32];

    float val[4];
    int cnt = 0;
    float m = -3.4028235e38f;
    for (int j = tid; j < L; j += 256) { float v = p[j]; val[cnt++] = v; m = fmaxf(m, v); }
    for (int o = 16; o; o >>= 1) m = fmaxf(m, __shfl_xor_sync(0xffffffffu, m, o));
    if ((tid & 31) == 0) sh[tid >> 5] = m;
    __syncthreads();
    if (tid < 32) {
        float v = (tid < 8) ? sh[tid] : -3.4028235e38f;
        for (int o = 4; o; o >>= 1) v = fmaxf(v, __shfl_xor_sync(0xffffffffu, v, o));
        if (tid == 0) sh[0] = v;
    }
    __syncthreads();
    m = sh[0];
    __syncthreads();
    float s = 0.f;
    for (int k = 0; k < cnt; k++) { val[k] = expf(val[k] - m); s += val[k]; }
    for (int o = 16; o; o >>= 1) s += __shfl_xor_sync(0xffffffffu, s, o);
    if ((tid & 31) == 0) sh[tid >> 5] = s;
    __syncthreads();
    if (tid < 32) {
        float v = (tid < 8) ? sh[tid] : 0.f;
        for (int o = 4; o; o >>= 1) v += __shfl_xor_sync(0xffffffffu, v, o);
        if (tid == 0) sh[0] = v;
    }
    __syncthreads();
    float inv = 1.0f / sh[0];
    __nv_bfloat16* ph = phi + (size_t)row * SEQ;
    __nv_bfloat16* pl = plo + (size_t)row * SEQ;
    for (int j = tid, k = 0; j < L; j += 256, k++) {
        float v = val[k] * inv;
        __nv_bfloat16 h, l;
        split2(v, h, l);
        ph[j] = h;
        pl[j] = l;
    }
    int jend = ((i >> 6) + 1) << 6;   // zero-fill diagonal tile remainder
    for (int j = L + tid; j < jend; j += 256) {
        ph[j] = __float2bfloat16(0.f);
        pl[j] = __float2bfloat16(0.f);
    }
}

// ---------------- tensorized P@V: writes split-bf16 attn-out (next GEMM's A) ----------------
__global__ void __launch_bounds__(128) pv_mma(
    const __nv_bfloat16* __restrict__ phi, const __nv_bfloat16* __restrict__ plo,
    const __nv_bfloat16* __restrict__ qkvhi, const __nv_bfloat16* __restrict__ qkvlo,
    __nv_bfloat16* __restrict__ ohi, __nv_bfloat16* __restrict__ olo)
{
    int it = blockIdx.x;
    int bh = blockIdx.y;
    int b = bh >> 4, h = bh & 15;

    __shared__ char sm[32768];   // Phi 0, Plo 8K, Vhi 16K, Vlo 24K
    uint32_t sb = smem_u32(sm);
    const int tid = threadIdx.x;
    const int wid = tid >> 5, lane = tid & 31;
    const int wm = (wid & 1) * 32, wn = (wid >> 1) * 32;

    float acc[2][4][4];
#pragma unroll
    for (int i = 0; i < 2; i++)
#pragma unroll
        for (int j = 0; j < 4; j++)
#pragma unroll
            for (int q = 0; q < 4; q++) acc[i][j][q] = 0.f;

    const size_t prow = (size_t)(bh * SEQ + it * 64) * SEQ;
    const size_t vrow = 2 * DMODEL + h * DHEAD;
    const int kend = (it + 1) * 64;

    for (int j0 = 0; j0 < kend; j0 += 64) {
#pragma unroll
        for (int i = 0; i < 4; i++) {
            int idx = tid + i * 128;
            int r = idx >> 3, q = idx & 7;
            uint32_t swo = sw128((uint32_t)(r * 128 + q * 16));
            size_t po = prow + (size_t)r * SEQ + j0 + q * 8;
            size_t vo = vrow + (size_t)(b * SEQ + j0 + r) * (3 * DMODEL) + q * 8;
            *(uint4*)(sm + swo)         = *(const uint4*)(phi + po);
            *(uint4*)(sm + 8192 + swo)  = *(const uint4*)(plo + po);
            *(uint4*)(sm + 16384 + swo) = *(const uint4*)(qkvhi + vo);
            *(uint4*)(sm + 24576 + swo) = *(const uint4*)(qkvlo + vo);
        }
        __syncthreads();
#pragma unroll
        for (int ks = 0; ks < 4; ks++) {
            uint32_t ah[2][4], al[2][4];
#pragma unroll
            for (int mt = 0; mt < 2; mt++) {
                int row = wm + mt * 16 + (lane & 15);
                int kb = ks * 16 + ((lane >> 4) << 3);
                uint32_t swo = sw128((uint32_t)(row * 128 + kb * 2));
                LDSM_X4(ah[mt][0], ah[mt][1], ah[mt][2], ah[mt][3], sb + swo);
                LDSM_X4(al[mt][0], al[mt][1], al[mt][2], al[mt][3], sb + 8192 + swo);
            }
            // B = V^T fragments via trans ldmatrix from V stored [tok, dh]
            uint32_t bfh[2][4], bfl[2][4];
#pragma unroll
            for (int np = 0; np < 2; np++) {
                int tok = ks * 16 + (lane & 7) + (((lane >> 3) & 1) << 3);
                int dh  = wn + np * 16 + ((lane >> 4) << 3);
                uint32_t swo = sw128((uint32_t)(tok * 128 + dh * 2));
                LDSM_X4_T(bfh[np][0], bfh[np][1], bfh[np][2], bfh[np][3], sb + 16384 + swo);
                LDSM_X4_T(bfl[np][0], bfl[np][1], bfl[np][2], bfl[np][3], sb + 24576 + swo);
            }
#pragma unroll
            for (int mt = 0; mt < 2; mt++)
#pragma unroll
                for (int np = 0; np < 2; np++) {
                    mma16816(acc[mt][np * 2 + 0], ah[mt], bfh[np][0], bfh[np][1]);
                    mma16816(acc[mt][np * 2 + 0], ah[mt], bfl[np][0], bfl[np][1]);
                    mma16816(acc[mt][np * 2 + 0], al[mt], bfh[np][0], bfh[np][1]);
                    mma16816(acc[mt][np * 2 + 1], ah[mt], bfh[np][2], bfh[np][3]);
                    mma16816(acc[mt][np * 2 + 1], ah[mt], bfl[np][2], bfl[np][3]);
                    mma16816(acc[mt][np * 2 + 1], al[mt], bfh[np][2], bfh[np][3]);
                }
        }
        __syncthreads();
    }

    // epilogue: split to bf16 hi/lo attn-out in merged-head layout [MROWS, DMODEL]
#pragma unroll
    for (int mt = 0; mt < 2; mt++) {
        int qrow = it * 64 + wm + mt * 16 + (lane >> 2);
        size_t base0 = (size_t)(b * SEQ + qrow) * DMODEL + h * DHEAD;
        size_t base1 = (size_t)(b * SEQ + qrow + 8) * DMODEL + h * DHEAD;
#pragma unroll
        for (int nt = 0; nt < 4; nt++) {
            int col = wn + nt * 8 + (lane & 3) * 2;
            __nv_bfloat162 h2, l2;
            split2(acc[mt][nt][0], h2.x, l2.x);
            split2(acc[mt][nt][1], h2.y, l2.y);
            *(__nv_bfloat162*)&ohi[base0 + col] = h2;
            *(__nv_bfloat162*)&olo[base0 + col] = l2;
            split2(acc[mt][nt][2], h2.x, l2.x);
            split2(acc[mt][nt][3], h2.y, l2.y);
            *(__nv_bfloat162*)&ohi[base1 + col] = h2;
            *(__nv_bfloat162*)&olo[base1 + col] = l2;
        }
    }
}

// ---------------- GEGLU: o = a * gelu_exact(gate) ----------------
__global__ void geglu_kernel(const float* __restrict__ h, float* __restrict__ o)
{
    int idx = blockIdx.x * blockDim.x + threadIdx.x;
    int m = idx >> 12, c = idx & 4095;
    float a = h[(size_t)m * (2 * FFI) + c];
    float g = h[(size_t)m * (2 * FFI) + FFI + c];
    float ge = 0.5f * g * (1.0f + erff(g * 0.70710678118654752f));
    o[idx] = a * ge;
}

// ---------------- orchestration ----------------
extern "C" void kernel_launch(void* const* d_in, const int* in_sizes, int n_in,
                              void* d_out, int out_size)
{
    const float* x_in   = (const float*)d_in[0];
    const float* qkv_w  = (const float*)d_in[1];
    const float* out_w  = (const float*)d_in[2];
    const float* ff_w1  = (const float*)d_in[3];
    const float* ff_w2  = (const float*)d_in[4];
    const float* attn_g = (const float*)d_in[5];
    const float* outln_g= (const float*)d_in[6];
    const float* ffn_g  = (const float*)d_in[7];
    const float* ffln_g = (const float*)d_in[8];
    const float* nin_g  = (const float*)d_in[9];
    const float* nout_g = (const float*)d_in[10];
    float* out = (float*)d_out;

    float *xbuf, *Sb, *proj, *ff1, *geg;
    __nv_bfloat16 *ahi, *alo, *bhi, *blo, *qhi, *qlo, *phi, *plo;
    cudaGetSymbolAddress((void**)&xbuf,  g_xbuf);
    cudaGetSymbolAddress((void**)&Sb,    g_S);
    cudaGetSymbolAddress((void**)&proj,  g_proj);
    cudaGetSymbolAddress((void**)&ff1,   g_ff1);
    cudaGetSymbolAddress((void**)&geg,   g_geglu);
    cudaGetSymbolAddress((void**)&ahi,   g_ahi);
    cudaGetSymbolAddress((void**)&alo,   g_alo);
    cudaGetSymbolAddress((void**)&bhi,   g_bhi);
    cudaGetSymbolAddress((void**)&blo,   g_blo);
    cudaGetSymbolAddress((void**)&qhi,   g_qkvhi);
    cudaGetSymbolAddress((void**)&qlo,   g_qkvlo);
    cudaGetSymbolAddress((void**)&phi,   g_phi);
    cudaGetSymbolAddress((void**)&plo,   g_plo);

    cudaFuncSetAttribute(gemm_mma_bf16x3, cudaFuncAttributeMaxDynamicSharedMemorySize, GSMEM);

    const int M = MROWS;
    ln_kernel<<<M, 256>>>(x_in, nin_g, nullptr, xbuf, DMODEL);

    for (int l = 0; l < NDEPTH; l++) {
        // ---- attention block ----
        ln_split<<<M, 256>>>(xbuf, attn_g + (size_t)l * DMODEL, ahi, alo, DMODEL);
        cvt_wt_t<<<dim3(3 * DMODEL / 32, DMODEL / 32), dim3(32, 8)>>>(
            qkv_w + (size_t)l * DMODEL * 3 * DMODEL, bhi, blo, DMODEL, 3 * DMODEL);
        gemm_mma_bf16x3<<<dim3(3 * DMODEL / GBN, M / GBM), 256, GSMEM>>>(
            ahi, alo, bhi, blo, nullptr, qhi, qlo, nullptr, M, 3 * DMODEL, DMODEL);

        qk_mma<<<dim3(16, 16, BH), 128>>>(qhi, qlo, Sb);
        softmax_split<<<BH * SEQ, 256>>>(Sb, phi, plo);
        pv_mma<<<dim3(16, BH), 128>>>(phi, plo, qhi, qlo, ahi, alo);

        cvt_wt_t<<<dim3(DMODEL / 32, DMODEL / 32), dim3(32, 8)>>>(
            out_w + (size_t)l * DMODEL * DMODEL, bhi, blo, DMODEL, DMODEL);
        gemm_mma_bf16x3<<<dim3(DMODEL / GBN, M / GBM), 256, GSMEM>>>(
            ahi, alo, bhi, blo, proj, nullptr, nullptr, nullptr, M, DMODEL, DMODEL);
        ln_kernel<<<M, 256>>>(proj, outln_g + (size_t)l * DMODEL, xbuf, xbuf, DMODEL);

        // ---- GEGLU feedforward ----
        ln_split<<<M, 256>>>(xbuf, ffn_g + (size_t)l * DMODEL, ahi, alo, DMODEL);
        cvt_wt_t<<<dim3(2 * FFI / 32, DMODEL / 32), dim3(32, 8)>>>(
            ff_w1 + (size_t)l * DMODEL * 2 * FFI, bhi, blo, DMODEL, 2 * FFI);
        gemm_mma_bf16x3<<<dim3(2 * FFI / GBN, M / GBM), 256, GSMEM>>>(
            ahi, alo, bhi, blo, ff1, nullptr, nullptr, nullptr, M, 2 * FFI, DMODEL);
        geglu_kernel<<<(M * FFI) / 256, 256>>>(ff1, geg);
        ln_split<<<M, 256>>>(geg, ffln_g + (size_t)l * FFI, ahi, alo, FFI);
        cvt_wt_t<<<dim3(DMODEL / 32, FFI / 32), dim3(32, 8)>>>(
            ff_w2 + (size_t)l * FFI * DMODEL, bhi, blo, FFI, DMODEL);
        gemm_mma_bf16x3<<<dim3(DMODEL / GBN, M / GBM), 256, GSMEM>>>(
            ahi, alo, bhi, blo, xbuf, nullptr, nullptr, xbuf, M, DMODEL, FFI);
    }
    ln_kernel<<<M, 256>>>(xbuf, nout_g, nullptr, out, DMODEL);
}

// round 6
// speedup vs baseline: 4.0810x; 1.3114x over previous
#include <cuda_runtime.h>
#include <cuda_bf16.h>
#include <math.h>
#include <stdint.h>

typedef unsigned long long ull;

// ---------------- model dims ----------------
#define NDEPTH 6
#define DMODEL 1024
#define NHEADS 16
#define DHEAD  64
#define SEQ    1024
#define BATCH  4
#define MROWS  (BATCH*SEQ)        // 4096
#define FFI    4096               // FF_INNER
#define BH     (BATCH*NHEADS)     // 64

// ---------------- scratch (static device memory; no allocs allowed) ----------------
__device__ float g_xbuf [MROWS*DMODEL];
__device__ float g_S    [(size_t)BH*SEQ*SEQ];     // fp32 scores
__device__ float g_proj [MROWS*DMODEL];
__device__ float g_ff1  [(size_t)MROWS*2*FFI];

__device__ __nv_bfloat16 g_ahi[(size_t)MROWS*FFI];       // GEMM A operand (split)
__device__ __nv_bfloat16 g_alo[(size_t)MROWS*FFI];
__device__ __nv_bfloat16 g_bhi[(size_t)(2*FFI)*DMODEL];  // weights [N,K] split
__device__ __nv_bfloat16 g_blo[(size_t)(2*FFI)*DMODEL];
__device__ __nv_bfloat16 g_qkvhi[(size_t)MROWS*3*DMODEL];
__device__ __nv_bfloat16 g_qkvlo[(size_t)MROWS*3*DMODEL];
__device__ __nv_bfloat16 g_phi[(size_t)BH*SEQ*SEQ];      // probs split
__device__ __nv_bfloat16 g_plo[(size_t)BH*SEQ*SEQ];

// ---------------- helpers ----------------
__device__ __forceinline__ uint32_t smem_u32(const void* p) {
    uint32_t a;
    asm("{ .reg .u64 t; cvta.to.shared.u64 t, %1; cvt.u32.u64 %0, t; }" : "=r"(a) : "l"(p));
    return a;
}
__device__ __forceinline__ void mma16816(float* c, const uint32_t* a, uint32_t b0, uint32_t b1) {
    asm volatile(
        "mma.sync.aligned.m16n8k16.row.col.f32.bf16.bf16.f32 "
        "{%0,%1,%2,%3}, {%4,%5,%6,%7}, {%8,%9}, {%0,%1,%2,%3};"
        : "+f"(c[0]), "+f"(c[1]), "+f"(c[2]), "+f"(c[3])
        : "r"(a[0]), "r"(a[1]), "r"(a[2]), "r"(a[3]), "r"(b0), "r"(b1));
}
#define LDSM_X4(r0, r1, r2, r3, addr) \
    asm volatile("ldmatrix.sync.aligned.m8n8.x4.shared.b16 {%0,%1,%2,%3}, [%4];" \
                 : "=r"(r0), "=r"(r1), "=r"(r2), "=r"(r3) : "r"(addr))
#define LDSM_X4_T(r0, r1, r2, r3, addr) \
    asm volatile("ldmatrix.sync.aligned.m8n8.x4.trans.shared.b16 {%0,%1,%2,%3}, [%4];" \
                 : "=r"(r0), "=r"(r1), "=r"(r2), "=r"(r3) : "r"(addr))
#define CP_ASYNC16(saddr, gptr) \
    asm volatile("cp.async.cg.shared.global [%0], [%1], 16;" :: "r"(saddr), "l"(gptr))
__device__ __forceinline__ uint32_t sw128(uint32_t off) { return off ^ ((off >> 3) & 0x70u); }
__device__ __forceinline__ void split2(float v, __nv_bfloat16& h, __nv_bfloat16& l) {
    h = __float2bfloat16(v);
    l = __float2bfloat16(v - __bfloat162float(h));
}

// ---------------- split-bf16 tensor-core GEMM ----------------
// C = Ahi*Bhi + Alo*Bhi + Ahi*Blo  (three K-segments, one fp32 accumulator)
// 128x128 tile, BK=64, 256 thr (8 warps, 32x64 warptile), 3-stage cp.async,
// 2 CTAs/SM via launch bounds (regs capped at 128).
#define GBM 128
#define GBN 128
#define GKC 64
#define NSTAGE 3
#define STAGE_BYTES 32768
#define GSMEM (NSTAGE*STAGE_BYTES + 1024)

__global__ void __launch_bounds__(256, 2) gemm_mma_bf16x3(
    const __nv_bfloat16* __restrict__ Ahi, const __nv_bfloat16* __restrict__ Alo,
    const __nv_bfloat16* __restrict__ Bhi, const __nv_bfloat16* __restrict__ Blo,
    float* __restrict__ C, __nv_bfloat16* __restrict__ Chi, __nv_bfloat16* __restrict__ Clo,
    const float* __restrict__ resid, int M, int N, int K)
{
    extern __shared__ char dsm[];
    const int tid = threadIdx.x;
    const int wid = tid >> 5, lane = tid & 31;
    const int bm = blockIdx.y * GBM, bn = blockIdx.x * GBN;
    const int m0 = (wid & 3) * 32;
    const int n0 = (wid >> 2) * 64;

    uint32_t raw = smem_u32(dsm);
    uint32_t base = (raw + 1023u) & ~1023u;
    char* smbase = dsm + (base - raw);

    const int segC = K / GKC;
    const int NC = 3 * segC;

    float acc[2][8][4];
#pragma unroll
    for (int i = 0; i < 2; i++)
#pragma unroll
        for (int j = 0; j < 8; j++)
#pragma unroll
            for (int q = 0; q < 4; q++) acc[i][j][q] = 0.f;

    // per-thread load coords (fixed across chunks)
    const int lr = tid >> 3, lq = tid & 7;                 // row 0..31 (x4 strided), col-16B
    const uint32_t lswo = sw128((uint32_t)(lr * 128 + lq * 16));

    auto issue = [&](int c) {
        int seg = c / segC;
        int kc = (c - seg * segC) * GKC;
        const __nv_bfloat16* Ag = (seg == 1) ? Alo : Ahi;
        const __nv_bfloat16* Bg = (seg == 2) ? Blo : Bhi;
        uint32_t abase = base + (uint32_t)(c % NSTAGE) * STAGE_BYTES;
        uint32_t bbase = abase + 16384u;
        const __nv_bfloat16* ag = Ag + (size_t)(bm + lr) * K + kc + lq * 8;
        const __nv_bfloat16* bg = Bg + (size_t)(bn + lr) * K + kc + lq * 8;
#pragma unroll
        for (int i = 0; i < 4; i++) {
            CP_ASYNC16(abase + lswo + i * 4096u, ag + (size_t)(i * 32) * K);
            CP_ASYNC16(bbase + lswo + i * 4096u, bg + (size_t)(i * 32) * K);
        }
        asm volatile("cp.async.commit_group;" ::: "memory");
    };

    issue(0);
    issue(1);

    for (int c = 0; c < NC; c++) {
        if (c + 2 < NC) {
            issue(c + 2);
            asm volatile("cp.async.wait_group 2;" ::: "memory");
        } else if (c + 1 < NC) {
            asm volatile("cp.async.wait_group 1;" ::: "memory");
        } else {
            asm volatile("cp.async.wait_group 0;" ::: "memory");
        }
        __syncthreads();

        uint32_t abase = base + (uint32_t)(c % NSTAGE) * STAGE_BYTES;
        uint32_t bbase = abase + 16384u;
#pragma unroll
        for (int ks = 0; ks < 4; ks++) {
            uint32_t a[2][4];
#pragma unroll
            for (int mt = 0; mt < 2; mt++) {
                int row = m0 + mt * 16 + (lane & 15);
                int kb = ks * 16 + ((lane >> 4) << 3);
                uint32_t ad = abase + sw128((uint32_t)(row * 128 + kb * 2));
                LDSM_X4(a[mt][0], a[mt][1], a[mt][2], a[mt][3], ad);
            }
            uint32_t b[4][4];
#pragma unroll
            for (int np = 0; np < 4; np++) {
                int nr = n0 + np * 16 + (lane & 7) + ((lane >> 4) << 3);
                int kb = ks * 16 + (((lane >> 3) & 1) << 3);
                uint32_t ad = bbase + sw128((uint32_t)(nr * 128 + kb * 2));
                LDSM_X4(b[np][0], b[np][1], b[np][2], b[np][3], ad);
            }
#pragma unroll
            for (int mt = 0; mt < 2; mt++)
#pragma unroll
                for (int np = 0; np < 4; np++) {
                    mma16816(acc[mt][np * 2 + 0], a[mt], b[np][0], b[np][1]);
                    mma16816(acc[mt][np * 2 + 1], a[mt], b[np][2], b[np][3]);
                }
        }
        __syncthreads();
    }

    // epilogue
#pragma unroll
    for (int mt = 0; mt < 2; mt++) {
        int row = bm + m0 + mt * 16 + (lane >> 2);
#pragma unroll
        for (int nt = 0; nt < 8; nt++) {
            int col = bn + n0 + nt * 8 + (lane & 3) * 2;
            size_t i0 = (size_t)row * N + col;
            size_t i1 = (size_t)(row + 8) * N + col;
            if (Chi) {
                __nv_bfloat162 h2, l2;
                split2(acc[mt][nt][0], h2.x, l2.x);
                split2(acc[mt][nt][1], h2.y, l2.y);
                *(__nv_bfloat162*)&Chi[i0] = h2;
                *(__nv_bfloat162*)&Clo[i0] = l2;
                split2(acc[mt][nt][2], h2.x, l2.x);
                split2(acc[mt][nt][3], h2.y, l2.y);
                *(__nv_bfloat162*)&Chi[i1] = h2;
                *(__nv_bfloat162*)&Clo[i1] = l2;
            } else if (resid) {
                float2 r0 = *(const float2*)&resid[i0];
                float2 r1 = *(const float2*)&resid[i1];
                *(float2*)&C[i0] = make_float2(acc[mt][nt][0] + r0.x, acc[mt][nt][1] + r0.y);
                *(float2*)&C[i1] = make_float2(acc[mt][nt][2] + r1.x, acc[mt][nt][3] + r1.y);
            } else {
                *(float2*)&C[i0] = make_float2(acc[mt][nt][0], acc[mt][nt][1]);
                *(float2*)&C[i1] = make_float2(acc[mt][nt][2], acc[mt][nt][3]);
            }
        }
    }
}

// ---------------- weights: W[K,N] row-major -> B[N,K] transposed split ----------------
__global__ void cvt_wt_t(const float* __restrict__ w, __nv_bfloat16* __restrict__ bhi,
                         __nv_bfloat16* __restrict__ blo, int K, int N)
{
    __shared__ float t[32][33];
    int k0 = blockIdx.y * 32, n0 = blockIdx.x * 32;
    int tx = threadIdx.x, ty = threadIdx.y;  // 32 x 8
    #pragma unroll
    for (int i = 0; i < 32; i += 8)
        t[ty + i][tx] = w[(size_t)(k0 + ty + i) * N + n0 + tx];
    __syncthreads();
    #pragma unroll
    for (int i = 0; i < 32; i += 8) {
        float v = t[tx][ty + i];
        __nv_bfloat16 h, l;
        split2(v, h, l);
        size_t o = (size_t)(n0 + ty + i) * K + k0 + tx;
        bhi[o] = h;
        blo[o] = l;
    }
}

// ---------------- LayerNorm helpers ----------------
__device__ __forceinline__ void red2(float& s, float& sq, int tid)
{
    __shared__ float sh[64];
    for (int o = 16; o; o >>= 1) { s += __shfl_xor_sync(0xffffffffu, s, o); sq += __shfl_xor_sync(0xffffffffu, sq, o); }
    int wid = tid >> 5, lid = tid & 31;
    if (lid == 0) { sh[wid] = s; sh[wid + 32] = sq; }
    __syncthreads();
    if (wid == 0) {
        float a = (lid < 8) ? sh[lid] : 0.f;
        float b = (lid < 8) ? sh[lid + 32] : 0.f;
        for (int o = 4; o; o >>= 1) { a += __shfl_xor_sync(0xffffffffu, a, o); b += __shfl_xor_sync(0xffffffffu, b, o); }
        if (lid == 0) { sh[0] = a; sh[1] = b; }
    }
    __syncthreads();
    s = sh[0];
    sq = sh[1];
}
__device__ __forceinline__ void ln_stats(const float* x, int D, int tid, float& mean, float& rstd)
{
    float s = 0.f, sq = 0.f;
    for (int c = tid; c < D; c += 256) { float v = x[c]; s += v; sq += v * v; }
    red2(s, sq, tid);
    mean = s / D;
    float var = sq / D - mean * mean;
    rstd = rsqrtf(var + 1e-5f);
}

// fp32 out, optional residual
__global__ void ln_kernel(const float* __restrict__ in, const float* __restrict__ g,
                          const float* __restrict__ res, float* __restrict__ out, int D)
{
    int row = blockIdx.x;
    const float* x = in + (size_t)row * D;
    float mean, rstd;
    ln_stats(x, D, threadIdx.x, mean, rstd);
    float* o = out + (size_t)row * D;
    const float* rr = res ? res + (size_t)row * D : nullptr;
    for (int c = threadIdx.x; c < D; c += 256) {
        float v = (x[c] - mean) * rstd * g[c];
        if (rr) v += rr[c];
        o[c] = v;
    }
}

// split-bf16 out (GEMM A operand)
__global__ void ln_split(const float* __restrict__ in, const float* __restrict__ g,
                         __nv_bfloat16* __restrict__ hi, __nv_bfloat16* __restrict__ lo, int D)
{
    int row = blockIdx.x;
    const float* x = in + (size_t)row * D;
    float mean, rstd;
    ln_stats(x, D, threadIdx.x, mean, rstd);
    for (int c = threadIdx.x; c < D; c += 256) {
        float v = (x[c] - mean) * rstd * g[c];
        __nv_bfloat16 h, l;
        split2(v, h, l);
        hi[(size_t)row * D + c] = h;
        lo[(size_t)row * D + c] = l;
    }
}

// fused GEGLU + LayerNorm -> split-bf16 (one block per row of FFI elements)
__global__ void geglu_ln_split(const float* __restrict__ ff1, const float* __restrict__ g,
                               __nv_bfloat16* __restrict__ hi, __nv_bfloat16* __restrict__ lo)
{
    int row = blockIdx.x;
    int tid = threadIdx.x;
    const float* arow = ff1 + (size_t)row * (2 * FFI);
    float val[FFI / 256];
    float s = 0.f, sq = 0.f;
#pragma unroll
    for (int k = 0; k < FFI / 256; k++) {
        int c = tid + k * 256;
        float a = arow[c];
        float gg = arow[FFI + c];
        float ge = 0.5f * gg * (1.0f + erff(gg * 0.70710678118654752f));
        float v = a * ge;
        val[k] = v;
        s += v;
        sq += v * v;
    }
    red2(s, sq, tid);
    float mean = s / FFI;
    float rstd = rsqrtf(sq / FFI - mean * mean + 1e-5f);
#pragma unroll
    for (int k = 0; k < FFI / 256; k++) {
        int c = tid + k * 256;
        float v = (val[k] - mean) * rstd * g[c];
        __nv_bfloat16 h, l;
        split2(v, h, l);
        hi[(size_t)row * FFI + c] = h;
        lo[(size_t)row * FFI + c] = l;
    }
}

// ---------------- tensorized QK^T: S = 0.125 * Q K^T, 64x64 tiles, split-bf16 ----------------
__global__ void __launch_bounds__(128) qk_mma(
    const __nv_bfloat16* __restrict__ qkvhi, const __nv_bfloat16* __restrict__ qkvlo,
    float* __restrict__ S)
{
    int bh = blockIdx.z; int b = bh >> 4, h = bh & 15;
    int jt = blockIdx.x, it = blockIdx.y;
    if (jt > it) return;

    __shared__ char sm[32768];   // Qhi 0, Qlo 8K, Khi 16K, Klo 24K
    uint32_t sb = smem_u32(sm);
    const int tid = threadIdx.x;
    const int wid = tid >> 5, lane = tid & 31;
    const int wm = (wid & 1) * 32, wn = (wid >> 1) * 32;

    const size_t qrow = (size_t)(b * SEQ + it * 64) * (3 * DMODEL) + h * DHEAD;
    const size_t krow = (size_t)(b * SEQ + jt * 64) * (3 * DMODEL) + DMODEL + h * DHEAD;
#pragma unroll
    for (int i = 0; i < 4; i++) {
        int idx = tid + i * 128;
        int r = idx >> 3, q = idx & 7;
        uint32_t swo = sw128((uint32_t)(r * 128 + q * 16));
        size_t qo = qrow + (size_t)r * (3 * DMODEL) + q * 8;
        size_t ko = krow + (size_t)r * (3 * DMODEL) + q * 8;
        *(uint4*)(sm + swo)          = *(const uint4*)(qkvhi + qo);
        *(uint4*)(sm + 8192 + swo)   = *(const uint4*)(qkvlo + qo);
        *(uint4*)(sm + 16384 + swo)  = *(const uint4*)(qkvhi + ko);
        *(uint4*)(sm + 24576 + swo)  = *(const uint4*)(qkvlo + ko);
    }
    __syncthreads();

    float acc[2][4][4];
#pragma unroll
    for (int i = 0; i < 2; i++)
#pragma unroll
        for (int j = 0; j < 4; j++)
#pragma unroll
            for (int q = 0; q < 4; q++) acc[i][j][q] = 0.f;

#pragma unroll
    for (int ks = 0; ks < 4; ks++) {
        uint32_t ah[2][4], al[2][4];
#pragma unroll
        for (int mt = 0; mt < 2; mt++) {
            int row = wm + mt * 16 + (lane & 15);
            int kb = ks * 16 + ((lane >> 4) << 3);
            uint32_t swo = sw128((uint32_t)(row * 128 + kb * 2));
            LDSM_X4(ah[mt][0], ah[mt][1], ah[mt][2], ah[mt][3], sb + swo);
            LDSM_X4(al[mt][0], al[mt][1], al[mt][2], al[mt][3], sb + 8192 + swo);
        }
        uint32_t bfh[2][4], bfl[2][4];
#pragma unroll
        for (int np = 0; np < 2; np++) {
            int nr = wn + np * 16 + (lane & 7) + ((lane >> 4) << 3);
            int kb = ks * 16 + (((lane >> 3) & 1) << 3);
            uint32_t swo = sw128((uint32_t)(nr * 128 + kb * 2));
            LDSM_X4(bfh[np][0], bfh[np][1], bfh[np][2], bfh[np][3], sb + 16384 + swo);
            LDSM_X4(bfl[np][0], bfl[np][1], bfl[np][2], bfl[np][3], sb + 24576 + swo);
        }
#pragma unroll
        for (int mt = 0; mt < 2; mt++)
#pragma unroll
            for (int np = 0; np < 2; np++) {
                mma16816(acc[mt][np * 2 + 0], ah[mt], bfh[np][0], bfh[np][1]);
                mma16816(acc[mt][np * 2 + 0], ah[mt], bfl[np][0], bfl[np][1]);
                mma16816(acc[mt][np * 2 + 0], al[mt], bfh[np][0], bfh[np][1]);
                mma16816(acc[mt][np * 2 + 1], ah[mt], bfh[np][2], bfh[np][3]);
                mma16816(acc[mt][np * 2 + 1], ah[mt], bfl[np][2], bfl[np][3]);
                mma16816(acc[mt][np * 2 + 1], al[mt], bfh[np][2], bfh[np][3]);
            }
    }

    const float scale = 0.125f;
    float* sbase = S + ((size_t)bh << 20);
#pragma unroll
    for (int mt = 0; mt < 2; mt++) {
        int row = it * 64 + wm + mt * 16 + (lane >> 2);
#pragma unroll
        for (int nt = 0; nt < 4; nt++) {
            int col = jt * 64 + wn + nt * 8 + (lane & 3) * 2;
            *(float2*)&sbase[(size_t)row * SEQ + col] =
                make_float2(acc[mt][nt][0] * scale, acc[mt][nt][1] * scale);
            *(float2*)&sbase[(size_t)(row + 8) * SEQ + col] =
                make_float2(acc[mt][nt][2] * scale, acc[mt][nt][3] * scale);
        }
    }
}

// ---------------- row softmax -> split-bf16 P ----------------
__global__ void softmax_split(const float* __restrict__ S,
                              __nv_bfloat16* __restrict__ phi, __nv_bfloat16* __restrict__ plo)
{
    int row = blockIdx.x;            // bh*1024 + i
    int i = row & (SEQ - 1);
    const float* p = S + (size_t)row * SEQ;
    int L = i + 1;
    int tid = threadIdx.x;
    __shared__ float sh[32];

    float val[4];
    int cnt = 0;
    float m = -3.4028235e38f;
    for (int j = tid; j < L; j += 256) { float v = p[j]; val[cnt++] = v; m = fmaxf(m, v); }
    for (int o = 16; o; o >>= 1) m = fmaxf(m, __shfl_xor_sync(0xffffffffu, m, o));
    if ((tid & 31) == 0) sh[tid >> 5] = m;
    __syncthreads();
    if (tid < 32) {
        float v = (tid < 8) ? sh[tid] : -3.4028235e38f;
        for (int o = 4; o; o >>= 1) v = fmaxf(v, __shfl_xor_sync(0xffffffffu, v, o));
        if (tid == 0) sh[0] = v;
    }
    __syncthreads();
    m = sh[0];
    __syncthreads();
    float s = 0.f;
    for (int k = 0; k < cnt; k++) { val[k] = expf(val[k] - m); s += val[k]; }
    for (int o = 16; o; o >>= 1) s += __shfl_xor_sync(0xffffffffu, s, o);
    if ((tid & 31) == 0) sh[tid >> 5] = s;
    __syncthreads();
    if (tid < 32) {
        float v = (tid < 8) ? sh[tid] : 0.f;
        for (int o = 4; o; o >>= 1) v += __shfl_xor_sync(0xffffffffu, v, o);
        if (tid == 0) sh[0] = v;
    }
    __syncthreads();
    float inv = 1.0f / sh[0];
    __nv_bfloat16* ph = phi + (size_t)row * SEQ;
    __nv_bfloat16* pl = plo + (size_t)row * SEQ;
    for (int j = tid, k = 0; j < L; j += 256, k++) {
        float v = val[k] * inv;
        __nv_bfloat16 h, l;
        split2(v, h, l);
        ph[j] = h;
        pl[j] = l;
    }
    int jend = ((i >> 6) + 1) << 6;   // zero-fill diagonal tile remainder
    for (int j = L + tid; j < jend; j += 256) {
        ph[j] = __float2bfloat16(0.f);
        pl[j] = __float2bfloat16(0.f);
    }
}

// ---------------- tensorized P@V: writes split-bf16 attn-out ----------------
__global__ void __launch_bounds__(128) pv_mma(
    const __nv_bfloat16* __restrict__ phi, const __nv_bfloat16* __restrict__ plo,
    const __nv_bfloat16* __restrict__ qkvhi, const __nv_bfloat16* __restrict__ qkvlo,
    __nv_bfloat16* __restrict__ ohi, __nv_bfloat16* __restrict__ olo)
{
    int it = blockIdx.x;
    int bh = blockIdx.y;
    int b = bh >> 4, h = bh & 15;

    __shared__ char sm[32768];   // Phi 0, Plo 8K, Vhi 16K, Vlo 24K
    uint32_t sb = smem_u32(sm);
    const int tid = threadIdx.x;
    const int wid = tid >> 5, lane = tid & 31;
    const int wm = (wid & 1) * 32, wn = (wid >> 1) * 32;

    float acc[2][4][4];
#pragma unroll
    for (int i = 0; i < 2; i++)
#pragma unroll
        for (int j = 0; j < 4; j++)
#pragma unroll
            for (int q = 0; q < 4; q++) acc[i][j][q] = 0.f;

    const size_t prow = (size_t)(bh * SEQ + it * 64) * SEQ;
    const size_t vrow = 2 * DMODEL + h * DHEAD;
    const int kend = (it + 1) * 64;

    for (int j0 = 0; j0 < kend; j0 += 64) {
#pragma unroll
        for (int i = 0; i < 4; i++) {
            int idx = tid + i * 128;
            int r = idx >> 3, q = idx & 7;
            uint32_t swo = sw128((uint32_t)(r * 128 + q * 16));
            size_t po = prow + (size_t)r * SEQ + j0 + q * 8;
            size_t vo = vrow + (size_t)(b * SEQ + j0 + r) * (3 * DMODEL) + q * 8;
            *(uint4*)(sm + swo)         = *(const uint4*)(phi + po);
            *(uint4*)(sm + 8192 + swo)  = *(const uint4*)(plo + po);
            *(uint4*)(sm + 16384 + swo) = *(const uint4*)(qkvhi + vo);
            *(uint4*)(sm + 24576 + swo) = *(const uint4*)(qkvlo + vo);
        }
        __syncthreads();
#pragma unroll
        for (int ks = 0; ks < 4; ks++) {
            uint32_t ah[2][4], al[2][4];
#pragma unroll
            for (int mt = 0; mt < 2; mt++) {
                int row = wm + mt * 16 + (lane & 15);
                int kb = ks * 16 + ((lane >> 4) << 3);
                uint32_t swo = sw128((uint32_t)(row * 128 + kb * 2));
                LDSM_X4(ah[mt][0], ah[mt][1], ah[mt][2], ah[mt][3], sb + swo);
                LDSM_X4(al[mt][0], al[mt][1], al[mt][2], al[mt][3], sb + 8192 + swo);
            }
            uint32_t bfh[2][4], bfl[2][4];
#pragma unroll
            for (int np = 0; np < 2; np++) {
                int tok = ks * 16 + (lane & 7) + (((lane >> 3) & 1) << 3);
                int dh  = wn + np * 16 + ((lane >> 4) << 3);
                uint32_t swo = sw128((uint32_t)(tok * 128 + dh * 2));
                LDSM_X4_T(bfh[np][0], bfh[np][1], bfh[np][2], bfh[np][3], sb + 16384 + swo);
                LDSM_X4_T(bfl[np][0], bfl[np][1], bfl[np][2], bfl[np][3], sb + 24576 + swo);
            }
#pragma unroll
            for (int mt = 0; mt < 2; mt++)
#pragma unroll
                for (int np = 0; np < 2; np++) {
                    mma16816(acc[mt][np * 2 + 0], ah[mt], bfh[np][0], bfh[np][1]);
                    mma16816(acc[mt][np * 2 + 0], ah[mt], bfl[np][0], bfl[np][1]);
                    mma16816(acc[mt][np * 2 + 0], al[mt], bfh[np][0], bfh[np][1]);
                    mma16816(acc[mt][np * 2 + 1], ah[mt], bfh[np][2], bfh[np][3]);
                    mma16816(acc[mt][np * 2 + 1], ah[mt], bfl[np][2], bfl[np][3]);
                    mma16816(acc[mt][np * 2 + 1], al[mt], bfh[np][2], bfh[np][3]);
                }
        }
        __syncthreads();
    }

    // epilogue: split to bf16 hi/lo attn-out in merged-head layout [MROWS, DMODEL]
#pragma unroll
    for (int mt = 0; mt < 2; mt++) {
        int qrow = it * 64 + wm + mt * 16 + (lane >> 2);
        size_t base0 = (size_t)(b * SEQ + qrow) * DMODEL + h * DHEAD;
        size_t base1 = (size_t)(b * SEQ + qrow + 8) * DMODEL + h * DHEAD;
#pragma unroll
        for (int nt = 0; nt < 4; nt++) {
            int col = wn + nt * 8 + (lane & 3) * 2;
            __nv_bfloat162 h2, l2;
            split2(acc[mt][nt][0], h2.x, l2.x);
            split2(acc[mt][nt][1], h2.y, l2.y);
            *(__nv_bfloat162*)&ohi[base0 + col] = h2;
            *(__nv_bfloat162*)&olo[base0 + col] = l2;
            split2(acc[mt][nt][2], h2.x, l2.x);
            split2(acc[mt][nt][3], h2.y, l2.y);
            *(__nv_bfloat162*)&ohi[base1 + col] = h2;
            *(__nv_bfloat162*)&olo[base1 + col] = l2;
        }
    }
}

// ---------------- orchestration ----------------
extern "C" void kernel_launch(void* const* d_in, const int* in_sizes, int n_in,
                              void* d_out, int out_size)
{
    const float* x_in   = (const float*)d_in[0];
    const float* qkv_w  = (const float*)d_in[1];
    const float* out_w  = (const float*)d_in[2];
    const float* ff_w1  = (const float*)d_in[3];
    const float* ff_w2  = (const float*)d_in[4];
    const float* attn_g = (const float*)d_in[5];
    const float* outln_g= (const float*)d_in[6];
    const float* ffn_g  = (const float*)d_in[7];
    const float* ffln_g = (const float*)d_in[8];
    const float* nin_g  = (const float*)d_in[9];
    const float* nout_g = (const float*)d_in[10];
    float* out = (float*)d_out;

    float *xbuf, *Sb, *proj, *ff1;
    __nv_bfloat16 *ahi, *alo, *bhi, *blo, *qhi, *qlo, *phi, *plo;
    cudaGetSymbolAddress((void**)&xbuf,  g_xbuf);
    cudaGetSymbolAddress((void**)&Sb,    g_S);
    cudaGetSymbolAddress((void**)&proj,  g_proj);
    cudaGetSymbolAddress((void**)&ff1,   g_ff1);
    cudaGetSymbolAddress((void**)&ahi,   g_ahi);
    cudaGetSymbolAddress((void**)&alo,   g_alo);
    cudaGetSymbolAddress((void**)&bhi,   g_bhi);
    cudaGetSymbolAddress((void**)&blo,   g_blo);
    cudaGetSymbolAddress((void**)&qhi,   g_qkvhi);
    cudaGetSymbolAddress((void**)&qlo,   g_qkvlo);
    cudaGetSymbolAddress((void**)&phi,   g_phi);
    cudaGetSymbolAddress((void**)&plo,   g_plo);

    cudaFuncSetAttribute(gemm_mma_bf16x3, cudaFuncAttributeMaxDynamicSharedMemorySize, GSMEM);

    const int M = MROWS;
    ln_kernel<<<M, 256>>>(x_in, nin_g, nullptr, xbuf, DMODEL);

    for (int l = 0; l < NDEPTH; l++) {
        // ---- attention block ----
        ln_split<<<M, 256>>>(xbuf, attn_g + (size_t)l * DMODEL, ahi, alo, DMODEL);
        cvt_wt_t<<<dim3(3 * DMODEL / 32, DMODEL / 32), dim3(32, 8)>>>(
            qkv_w + (size_t)l * DMODEL * 3 * DMODEL, bhi, blo, DMODEL, 3 * DMODEL);
        gemm_mma_bf16x3<<<dim3(3 * DMODEL / GBN, M / GBM), 256, GSMEM>>>(
            ahi, alo, bhi, blo, nullptr, qhi, qlo, nullptr, M, 3 * DMODEL, DMODEL);

        qk_mma<<<dim3(16, 16, BH), 128>>>(qhi, qlo, Sb);
        softmax_split<<<BH * SEQ, 256>>>(Sb, phi, plo);
        pv_mma<<<dim3(16, BH), 128>>>(phi, plo, qhi, qlo, ahi, alo);

        cvt_wt_t<<<dim3(DMODEL / 32, DMODEL / 32), dim3(32, 8)>>>(
            out_w + (size_t)l * DMODEL * DMODEL, bhi, blo, DMODEL, DMODEL);
        gemm_mma_bf16x3<<<dim3(DMODEL / GBN, M / GBM), 256, GSMEM>>>(
            ahi, alo, bhi, blo, proj, nullptr, nullptr, nullptr, M, DMODEL, DMODEL);
        ln_kernel<<<M, 256>>>(proj, outln_g + (size_t)l * DMODEL, xbuf, xbuf, DMODEL);

        // ---- GEGLU feedforward ----
        ln_split<<<M, 256>>>(xbuf, ffn_g + (size_t)l * DMODEL, ahi, alo, DMODEL);
        cvt_wt_t<<<dim3(2 * FFI / 32, DMODEL / 32), dim3(32, 8)>>>(
            ff_w1 + (size_t)l * DMODEL * 2 * FFI, bhi, blo, DMODEL, 2 * FFI);
        gemm_mma_bf16x3<<<dim3(2 * FFI / GBN, M / GBM), 256, GSMEM>>>(
            ahi, alo, bhi, blo, ff1, nullptr, nullptr, nullptr, M, 2 * FFI, DMODEL);
        geglu_ln_split<<<M, 256>>>(ff1, ffln_g + (size_t)l * FFI, ahi, alo);
        cvt_wt_t<<<dim3(DMODEL / 32, FFI / 32), dim3(32, 8)>>>(
            ff_w2 + (size_t)l * FFI * DMODEL, bhi, blo, FFI, DMODEL);
        gemm_mma_bf16x3<<<dim3(DMODEL / GBN, M / GBM), 256, GSMEM>>>(
            ahi, alo, bhi, blo, xbuf, nullptr, nullptr, xbuf, M, DMODEL, FFI);
    }
    ln_kernel<<<M, 256>>>(xbuf, nout_g, nullptr, out, DMODEL);
}